// round 3
// baseline (speedup 1.0000x reference)
#include <cuda_runtime.h>
#include <cuda_bf16.h>

// Problem constants
#define BB 8
#define SS 1024
#define DD 768
#define HH 12
#define HD 64

// Scratch (no cudaMalloc allowed)
__device__ float g_q[BB * HH * SS * HD];     // (B,H,S,HD)
__device__ float g_k[BB * HH * SS * HD];
__device__ float g_v[BB * HH * SS * HD];
__device__ float g_rel[BB * SS * SS];        // rel_attn, head-independent
__device__ int   g_mask_mode;                // 0=f32, 1=i32, 2=u8

// ---------------------------------------------------------------------------
// Mask dtype detection: jax bool mask may be serialized as f32 / i32 / u8.
// f32 1.0f bytes (LE): 00 00 80 3F  -> 0x80 at off%4==2, 0x3F at off%4==3
// i32 1    bytes:      01 00 00 00  -> nonzero only at off%4==0
// u8  0/1:             nonzero 1s at all offsets
// ---------------------------------------------------------------------------
__global__ void detect_mask_kernel(const unsigned char* __restrict__ m) {
    __shared__ int f32flag, nz123;
    if (threadIdx.x == 0) { f32flag = 0; nz123 = 0; }
    __syncthreads();
    for (int i = threadIdx.x; i < 65536; i += blockDim.x) {
        unsigned char v = m[i];
        if (v) {
            int r = i & 3;
            if ((r == 3 && v == 0x3F) || (r == 2 && v == 0x80)) atomicOr(&f32flag, 1);
            if (r != 0) atomicOr(&nz123, 1);
        }
    }
    __syncthreads();
    if (threadIdx.x == 0)
        g_mask_mode = f32flag ? 0 : (nz123 ? 2 : 1);
}

__device__ __forceinline__ float maskAt(const void* m, long i, int mode) {
    if (mode == 0) return ((const float*)m)[i];
    if (mode == 1) return (float)((const int*)m)[i];
    return (float)((const unsigned char*)m)[i];
}

// ---------------------------------------------------------------------------
// Projection GEMM: Y = X @ W^T + bias, scattered to (B,H,S,HD).
// M=8192, N=768, K=768. Tile 128x64, micro 8x4, 256 threads.
// ---------------------------------------------------------------------------
__global__ __launch_bounds__(256) void proj_kernel(
    const float* __restrict__ X, const float* __restrict__ W,
    const float* __restrict__ bias, int which)
{
    __shared__ float As[16][136];  // [kk][m], padded
    __shared__ float Bs[16][68];   // [kk][n], padded

    float* dst = (which == 0) ? g_q : (which == 1) ? g_k : g_v;

    const int tx = threadIdx.x & 15;
    const int ty = threadIdx.x >> 4;
    const int m0 = blockIdx.y * 128;
    const int n0 = blockIdx.x * 64;

    float acc[8][4];
#pragma unroll
    for (int i = 0; i < 8; i++)
#pragma unroll
        for (int j = 0; j < 4; j++) acc[i][j] = 0.f;

    for (int k0 = 0; k0 < DD; k0 += 16) {
        // load A tile: 128 rows x 16 k
        {
            int m = threadIdx.x >> 1;
            int half = threadIdx.x & 1;
            const float* g = X + (long)(m0 + m) * DD + k0 + half * 8;
            float4 a0 = *(const float4*)g;
            float4 a1 = *(const float4*)(g + 4);
            int kb = half * 8;
            As[kb + 0][m] = a0.x; As[kb + 1][m] = a0.y;
            As[kb + 2][m] = a0.z; As[kb + 3][m] = a0.w;
            As[kb + 4][m] = a1.x; As[kb + 5][m] = a1.y;
            As[kb + 6][m] = a1.z; As[kb + 7][m] = a1.w;
        }
        // load B tile: 64 rows x 16 k
        {
            int n = threadIdx.x >> 2;
            int kq = threadIdx.x & 3;
            float4 bv = *(const float4*)(W + (long)(n0 + n) * DD + k0 + kq * 4);
            Bs[kq * 4 + 0][n] = bv.x; Bs[kq * 4 + 1][n] = bv.y;
            Bs[kq * 4 + 2][n] = bv.z; Bs[kq * 4 + 3][n] = bv.w;
        }
        __syncthreads();
#pragma unroll
        for (int kk = 0; kk < 16; kk++) {
            float4 a0 = *(const float4*)(&As[kk][ty * 8]);
            float4 a1 = *(const float4*)(&As[kk][ty * 8 + 4]);
            float4 b4 = *(const float4*)(&Bs[kk][tx * 4]);
            float a[8] = {a0.x, a0.y, a0.z, a0.w, a1.x, a1.y, a1.z, a1.w};
            float b[4] = {b4.x, b4.y, b4.z, b4.w};
#pragma unroll
            for (int i = 0; i < 8; i++)
#pragma unroll
                for (int j = 0; j < 4; j++)
                    acc[i][j] += a[i] * b[j];
        }
        __syncthreads();
    }

    float4 bb = *(const float4*)(bias + n0 + tx * 4);
    int h = blockIdx.x;  // n0 = h*64, NT==HD
#pragma unroll
    for (int i = 0; i < 8; i++) {
        int m = m0 + ty * 8 + i;
        int b = m >> 10, s = m & 1023;
        float4 o = make_float4(acc[i][0] + bb.x, acc[i][1] + bb.y,
                               acc[i][2] + bb.z, acc[i][3] + bb.w);
        *(float4*)(dst + (((long)(b * HH + h) << 10) + s) * HD + tx * 4) = o;
    }
}

// ---------------------------------------------------------------------------
// rel_attn: per (b, q) row softmax of (mask ? rel : -1e4). Head-independent.
// grid = B*S blocks, 256 threads, 4 cols/thread.
// ---------------------------------------------------------------------------
__global__ __launch_bounds__(256) void relattn_kernel(
    const float* __restrict__ rel, const void* __restrict__ mask)
{
    const int row = blockIdx.x;
    const int tid = threadIdx.x;
    const int mode = g_mask_mode;
    const long base = (long)row * SS;

    float4 r4 = *(const float4*)(rel + base + tid * 4);
    float rr[4] = {r4.x, r4.y, r4.z, r4.w};
    float v[4];
#pragma unroll
    for (int u = 0; u < 4; u++) {
        float m = maskAt(mask, base + tid * 4 + u, mode);
        v[u] = (m != 0.f) ? rr[u] : -1.0e4f;
    }

    __shared__ float red[8];
    float mx = fmaxf(fmaxf(v[0], v[1]), fmaxf(v[2], v[3]));
#pragma unroll
    for (int o = 16; o; o >>= 1) mx = fmaxf(mx, __shfl_xor_sync(0xffffffffu, mx, o));
    if ((tid & 31) == 0) red[tid >> 5] = mx;
    __syncthreads();
    float bm = red[0];
#pragma unroll
    for (int i = 1; i < 8; i++) bm = fmaxf(bm, red[i]);
    __syncthreads();

    float e[4];
    float s = 0.f;
#pragma unroll
    for (int u = 0; u < 4; u++) { e[u] = __expf(v[u] - bm); s += e[u]; }
#pragma unroll
    for (int o = 16; o; o >>= 1) s += __shfl_xor_sync(0xffffffffu, s, o);
    if ((tid & 31) == 0) red[tid >> 5] = s;
    __syncthreads();
    float tot = 0.f;
#pragma unroll
    for (int i = 0; i < 8; i++) tot += red[i];
    float inv = 1.f / tot;

    float4 o4 = make_float4(e[0] * inv, e[1] * inv, e[2] * inv, e[3] * inv);
    *(float4*)(g_rel + base + tid * 4) = o4;
}

// ---------------------------------------------------------------------------
// Attention: block = (b, h, 16 query rows). Scores tile in smem.
// 256 threads = 16 q-rows x 16 lanes. Dynamic smem 89856B.
// ---------------------------------------------------------------------------
#define KPAD 76
#define ATTN_SMEM ((16 * KPAD + 64 * KPAD + 16 * 1024) * 4)

__global__ __launch_bounds__(256) void attn_kernel(
    const void* __restrict__ mask, const float* __restrict__ l1p,
    float* __restrict__ out0, float* __restrict__ probout)
{
    const int b = blockIdx.z, h = blockIdx.y, s0 = blockIdx.x * 16;
    const int tid = threadIdx.x;
    const int q = tid >> 4, j = tid & 15;
    const int mode = g_mask_mode;

    extern __shared__ float sm[];
    float* Qs = sm;                        // 16 x KPAD
    float* Ks = sm + 16 * KPAD;            // 64 x KPAD (reused for V)
    float* Sc = sm + (16 + 64) * KPAD;     // 16 x 1024

    const long bh = (long)(b * HH + h);
    const float* qbase = g_q + (bh * SS + s0) * HD;
    const float* kbase = g_k + bh * SS * HD;
    const float* vbase = g_v + bh * SS * HD;

    // load Q tile: 1 float4 per thread
    {
        int row = tid >> 4, d4 = tid & 15;
        float4 v = *(const float4*)(qbase + row * HD + d4 * 4);
        *(float4*)(Qs + row * KPAD + d4 * 4) = v;
    }

    // -------- Phase 1: scores = Q K^T / 8 --------
    for (int kc = 0; kc < 16; kc++) {
        __syncthreads();
        {   // load K chunk: 64 rows x 64 floats; 16 consecutive floats/thread
            int row = tid >> 2, c0 = (tid & 3) * 16;
            const float* g = kbase + (long)(kc * 64 + row) * HD + c0;
            float* p = Ks + row * KPAD + c0;
#pragma unroll
            for (int i = 0; i < 4; i++)
                *(float4*)(p + i * 4) = *(const float4*)(g + i * 4);
        }
        __syncthreads();
        float acc[4] = {0.f, 0.f, 0.f, 0.f};
        const float* qrow = Qs + q * KPAD;
#pragma unroll
        for (int d4 = 0; d4 < 16; d4++) {
            float4 qv = *(const float4*)(qrow + d4 * 4);
#pragma unroll
            for (int u = 0; u < 4; u++) {
                float4 kv = *(const float4*)(Ks + (j + 16 * u) * KPAD + d4 * 4);
                acc[u] += qv.x * kv.x + qv.y * kv.y + qv.z * kv.z + qv.w * kv.w;
            }
        }
#pragma unroll
        for (int u = 0; u < 4; u++)
            Sc[q * 1024 + kc * 64 + j + 16 * u] = acc[u] * 0.125f;
    }

    // -------- Phase 2: mask + softmax + blend with rel_attn, write prob ----
    const int sq = s0 + q;
    const long mbase = ((long)(b * SS + sq)) * SS;

    float mx = -3.0e38f;
#pragma unroll 4
    for (int t = 0; t < 64; t++) {
        int k = j + 16 * t;
        float s = Sc[q * 1024 + k];
        if (maskAt(mask, mbase + k, mode) != 0.f) s = -1.0e9f;
        Sc[q * 1024 + k] = s;
        mx = fmaxf(mx, s);
    }
#pragma unroll
    for (int o = 8; o; o >>= 1) mx = fmaxf(mx, __shfl_xor_sync(0xffffffffu, mx, o));

    float sum = 0.f;
#pragma unroll 4
    for (int t = 0; t < 64; t++) {
        int k = j + 16 * t;
        float e = __expf(Sc[q * 1024 + k] - mx);
        Sc[q * 1024 + k] = e;
        sum += e;
    }
#pragma unroll
    for (int o = 8; o; o >>= 1) sum += __shfl_xor_sync(0xffffffffu, sum, o);
    float inv = 1.f / sum;

    const float l1v = *l1p;
    const float w0 = 1.f - l1v;
    const float* relrow = g_rel + mbase;
    float* prow = probout + ((bh << 10) + sq) * (long)SS;
#pragma unroll 4
    for (int t = 0; t < 64; t++) {
        int k = j + 16 * t;
        float p = w0 * Sc[q * 1024 + k] * inv + l1v * relrow[k];
        Sc[q * 1024 + k] = p;
        prow[k] = p;
    }

    // -------- Phase 3: out = prob @ V --------
    float acc[4] = {0.f, 0.f, 0.f, 0.f};
    for (int vc = 0; vc < 16; vc++) {
        __syncthreads();  // also orders phase-2 Sc writes before cross-thread reads
        {
            int row = tid >> 2, c0 = (tid & 3) * 16;
            const float* g = vbase + (long)(vc * 64 + row) * HD + c0;
            float* p = Ks + row * KPAD + c0;
#pragma unroll
            for (int i = 0; i < 4; i++)
                *(float4*)(p + i * 4) = *(const float4*)(g + i * 4);
        }
        __syncthreads();
        const float* pr = Sc + q * 1024 + vc * 64;
#pragma unroll 8
        for (int kk = 0; kk < 64; kk++) {
            float p = pr[kk];
            float4 v = *(const float4*)(Ks + kk * KPAD + j * 4);
            acc[0] += p * v.x; acc[1] += p * v.y;
            acc[2] += p * v.z; acc[3] += p * v.w;
        }
    }
    *(float4*)(out0 + ((long)(b * SS + sq)) * DD + h * HD + j * 4) =
        make_float4(acc[0], acc[1], acc[2], acc[3]);
}

// ---------------------------------------------------------------------------
extern "C" void kernel_launch(void* const* d_in, const int* in_sizes, int n_in,
                              void* d_out, int out_size)
{
    const float* query = (const float*)d_in[0];
    const float* key_t = (const float*)d_in[1];
    const float* value = (const float*)d_in[2];
    const float* rel   = (const float*)d_in[3];
    const void*  mask  = d_in[4];
    const float* l1    = (const float*)d_in[5];
    const float* Wq = (const float*)d_in[6];
    const float* bq = (const float*)d_in[7];
    const float* Wk = (const float*)d_in[8];
    const float* bk = (const float*)d_in[9];
    const float* Wv = (const float*)d_in[10];
    const float* bv = (const float*)d_in[11];

    float* out0 = (float*)d_out;                        // (B,S,D)
    float* prob = out0 + (long)BB * SS * DD;            // (B,H,S,S)

    cudaFuncSetAttribute(attn_kernel,
                         cudaFuncAttributeMaxDynamicSharedMemorySize, ATTN_SMEM);

    detect_mask_kernel<<<1, 256>>>((const unsigned char*)mask);

    dim3 pgrid(DD / 64, (BB * SS) / 128);
    proj_kernel<<<pgrid, 256>>>(query, Wq, bq, 0);
    proj_kernel<<<pgrid, 256>>>(key_t, Wk, bk, 1);
    proj_kernel<<<pgrid, 256>>>(value, Wv, bv, 2);

    relattn_kernel<<<BB * SS, 256>>>(rel, mask);

    dim3 agrid(SS / 16, HH, BB);
    attn_kernel<<<agrid, 256, ATTN_SMEM>>>(mask, l1, out0, prob);
}

// round 5
// speedup vs baseline: 1.1981x; 1.1981x over previous
#include <cuda_runtime.h>
#include <cuda_bf16.h>

// Problem constants
#define BB 8
#define SS 1024
#define DD 768
#define HH 12
#define HD 64

// Scratch (no cudaMalloc allowed)
__device__ float g_q[BB * HH * SS * HD];     // (B,H,S,HD)
__device__ float g_k[BB * HH * SS * HD];
__device__ float g_v[BB * HH * SS * HD];
__device__ int   g_mask_mode;                // 0=f32, 1=i32, 2=u8

typedef unsigned long long ull;

// ---- packed f32x2 helpers (sm_103a FFMA2 path, PTX-only) -------------------
__device__ __forceinline__ ull pk2(float x) {
    ull r;
    asm("mov.b64 %0, {%1, %1};" : "=l"(r) : "r"(__float_as_uint(x)));
    return r;
}
__device__ __forceinline__ void fma2(ull& d, ull a, ull b) {
    asm("fma.rn.f32x2 %0, %1, %2, %0;" : "+l"(d) : "l"(a), "l"(b));
}
__device__ __forceinline__ float2 up2(ull v) {
    float2 f;
    f.x = __uint_as_float((unsigned)v);
    f.y = __uint_as_float((unsigned)(v >> 32));
    return f;
}

// ---------------------------------------------------------------------------
// Mask dtype detection: jax bool mask may be serialized as f32 / i32 / u8.
// ---------------------------------------------------------------------------
__global__ void detect_mask_kernel(const unsigned char* __restrict__ m) {
    __shared__ int f32flag, nz123;
    if (threadIdx.x == 0) { f32flag = 0; nz123 = 0; }
    __syncthreads();
    for (int i = threadIdx.x; i < 65536; i += blockDim.x) {
        unsigned char v = m[i];
        if (v) {
            int r = i & 3;
            if ((r == 3 && v == 0x3F) || (r == 2 && v == 0x80)) atomicOr(&f32flag, 1);
            if (r != 0) atomicOr(&nz123, 1);
        }
    }
    __syncthreads();
    if (threadIdx.x == 0)
        g_mask_mode = f32flag ? 0 : (nz123 ? 2 : 1);
}

__device__ __forceinline__ float maskAt(const void* m, long i, int mode) {
    if (mode == 0) return ((const float*)m)[i];
    if (mode == 1) return (float)((const int*)m)[i];
    return (float)((const unsigned char*)m)[i];
}

// ---------------------------------------------------------------------------
// Projection GEMM: Y = X @ W^T + bias, scattered to (B,H,S,HD).
// M=8192, N=768, K=768. Tile 128x64, micro 8x4 (as 8x2 packed pairs).
// ---------------------------------------------------------------------------
__global__ __launch_bounds__(256) void proj_kernel(
    const float* __restrict__ X, const float* __restrict__ W,
    const float* __restrict__ bias, int which)
{
    __shared__ float As[16][136];  // [kk][m]
    __shared__ float Bs[16][68];   // [kk][n]

    float* dst = (which == 0) ? g_q : (which == 1) ? g_k : g_v;

    const int tx = threadIdx.x & 15;
    const int ty = threadIdx.x >> 4;
    const int m0 = blockIdx.y * 128;
    const int n0 = blockIdx.x * 64;

    ull acc[8][2];
#pragma unroll
    for (int i = 0; i < 8; i++) { acc[i][0] = 0ull; acc[i][1] = 0ull; }

    for (int k0 = 0; k0 < DD; k0 += 16) {
        {
            int m = threadIdx.x >> 1;
            int half = threadIdx.x & 1;
            const float* g = X + (long)(m0 + m) * DD + k0 + half * 8;
            float4 a0 = *(const float4*)g;
            float4 a1 = *(const float4*)(g + 4);
            int kb = half * 8;
            As[kb + 0][m] = a0.x; As[kb + 1][m] = a0.y;
            As[kb + 2][m] = a0.z; As[kb + 3][m] = a0.w;
            As[kb + 4][m] = a1.x; As[kb + 5][m] = a1.y;
            As[kb + 6][m] = a1.z; As[kb + 7][m] = a1.w;
        }
        {
            int n = threadIdx.x >> 2;
            int kq = threadIdx.x & 3;
            float4 bv = *(const float4*)(W + (long)(n0 + n) * DD + k0 + kq * 4);
            Bs[kq * 4 + 0][n] = bv.x; Bs[kq * 4 + 1][n] = bv.y;
            Bs[kq * 4 + 2][n] = bv.z; Bs[kq * 4 + 3][n] = bv.w;
        }
        __syncthreads();
#pragma unroll
        for (int kk = 0; kk < 16; kk++) {
            float4 a0 = *(const float4*)(&As[kk][ty * 8]);
            float4 a1 = *(const float4*)(&As[kk][ty * 8 + 4]);
            ulonglong2 bp = *(const ulonglong2*)(&Bs[kk][tx * 4]);
            float a[8] = {a0.x, a0.y, a0.z, a0.w, a1.x, a1.y, a1.z, a1.w};
#pragma unroll
            for (int i = 0; i < 8; i++) {
                ull ai = pk2(a[i]);
                fma2(acc[i][0], ai, bp.x);
                fma2(acc[i][1], ai, bp.y);
            }
        }
        __syncthreads();
    }

    float4 bb = *(const float4*)(bias + n0 + tx * 4);
    int h = blockIdx.x;  // n0 = h*64, NT==HD
#pragma unroll
    for (int i = 0; i < 8; i++) {
        int m = m0 + ty * 8 + i;
        int b = m >> 10, s = m & 1023;
        float2 lo = up2(acc[i][0]), hi = up2(acc[i][1]);
        float4 o = make_float4(lo.x + bb.x, lo.y + bb.y, hi.x + bb.z, hi.y + bb.w);
        *(float4*)(dst + (((long)(b * HH + h) << 10) + s) * HD + tx * 4) = o;
    }
}

// ---------------------------------------------------------------------------
// Scores GEMM: S[bh,q,k] = (Q K^T) / 8, raw (unmasked), written to prob
// region as scratch. Tile 128(q) x 128(k), K-depth 64 loaded once.
// 256 threads, micro 8x8 (as 8x4 packed pairs). Dyn smem 67584 B.
// ---------------------------------------------------------------------------
#define SC_SMEM (2 * 64 * 132 * 4)

__global__ __launch_bounds__(256, 2) void score_kernel(float* __restrict__ prob)
{
    extern __shared__ float sm[];
    float* Qs = sm;              // [64][132]  (d-major: Qs[d][m])
    float* Ks = sm + 64 * 132;   // [64][132]

    const int tid = threadIdx.x;
    const int tx = tid & 15, ty = tid >> 4;
    const int bh = blockIdx.z;
    const int q0 = blockIdx.y * 128, k0 = blockIdx.x * 128;

    const float* qbase = g_q + ((long)bh * SS + q0) * HD;
    const float* kbase = g_k + ((long)bh * SS + k0) * HD;

    {   // load + transpose both tiles: 128 rows x 64 d each
        int m = tid >> 1, half = tid & 1;
        const float* gq = qbase + m * HD + half * 32;
        const float* gk = kbase + m * HD + half * 32;
#pragma unroll
        for (int i = 0; i < 8; i++) {
            float4 v = *(const float4*)(gq + i * 4);
            int d = half * 32 + i * 4;
            Qs[(d + 0) * 132 + m] = v.x; Qs[(d + 1) * 132 + m] = v.y;
            Qs[(d + 2) * 132 + m] = v.z; Qs[(d + 3) * 132 + m] = v.w;
            float4 w = *(const float4*)(gk + i * 4);
            Ks[(d + 0) * 132 + m] = w.x; Ks[(d + 1) * 132 + m] = w.y;
            Ks[(d + 2) * 132 + m] = w.z; Ks[(d + 3) * 132 + m] = w.w;
        }
    }
    __syncthreads();

    ull acc[8][4];
#pragma unroll
    for (int i = 0; i < 8; i++)
#pragma unroll
        for (int p = 0; p < 4; p++) acc[i][p] = 0ull;

#pragma unroll 4
    for (int d = 0; d < 64; d++) {
        const float* qr = Qs + d * 132;
        const float* kr = Ks + d * 132;
        float4 a0 = *(const float4*)(qr + ty * 8);
        float4 a1 = *(const float4*)(qr + ty * 8 + 4);
        ulonglong2 b0 = *(const ulonglong2*)(kr + tx * 4);        // k strip 0
        ulonglong2 b1 = *(const ulonglong2*)(kr + 64 + tx * 4);   // k strip 1
        float a[8] = {a0.x, a0.y, a0.z, a0.w, a1.x, a1.y, a1.z, a1.w};
#pragma unroll
        for (int i = 0; i < 8; i++) {
            ull ai = pk2(a[i]);
            fma2(acc[i][0], ai, b0.x);
            fma2(acc[i][1], ai, b0.y);
            fma2(acc[i][2], ai, b1.x);
            fma2(acc[i][3], ai, b1.y);
        }
    }

#pragma unroll
    for (int i = 0; i < 8; i++) {
        long row = ((long)bh * SS + q0 + ty * 8 + i) * SS;
        float2 p0 = up2(acc[i][0]), p1 = up2(acc[i][1]);
        float2 p2 = up2(acc[i][2]), p3 = up2(acc[i][3]);
        *(float4*)(prob + row + k0 + tx * 4) =
            make_float4(p0.x * 0.125f, p0.y * 0.125f, p1.x * 0.125f, p1.y * 0.125f);
        *(float4*)(prob + row + k0 + 64 + tx * 4) =
            make_float4(p2.x * 0.125f, p2.y * 0.125f, p3.x * 0.125f, p3.y * 0.125f);
    }
}

// ---------------------------------------------------------------------------
// Softmax + mask + rel-blend, in place on prob region.
// Block = (q, b); computes rel_attn ONCE per (b,q), then loops 12 heads.
// ---------------------------------------------------------------------------
__device__ __forceinline__ float bredMax(float v, volatile float* red) {
#pragma unroll
    for (int o = 16; o; o >>= 1) v = fmaxf(v, __shfl_xor_sync(0xffffffffu, v, o));
    if ((threadIdx.x & 31) == 0) red[threadIdx.x >> 5] = v;
    __syncthreads();
    float r = red[0];
#pragma unroll
    for (int i = 1; i < 8; i++) r = fmaxf(r, red[i]);
    __syncthreads();
    return r;
}
__device__ __forceinline__ float bredSum(float v, volatile float* red) {
#pragma unroll
    for (int o = 16; o; o >>= 1) v += __shfl_xor_sync(0xffffffffu, v, o);
    if ((threadIdx.x & 31) == 0) red[threadIdx.x >> 5] = v;
    __syncthreads();
    float r = 0.f;
#pragma unroll
    for (int i = 0; i < 8; i++) r += red[i];
    __syncthreads();
    return r;
}

__global__ __launch_bounds__(256) void softmax_kernel(
    const float* __restrict__ rel, const void* __restrict__ mask,
    const float* __restrict__ l1p, float* __restrict__ prob)
{
    __shared__ float relp[1024];   // l1 * rel_attn
    __shared__ float msk[1024];
    __shared__ float red[8];

    const int b = blockIdx.y, q = blockIdx.x, tid = threadIdx.x;
    const int mode = g_mask_mode;
    const long mbase = ((long)(b * SS + q)) * SS;

    // ---- rel_attn row (head-independent), computed once ----
    float4 r4 = *(const float4*)(rel + mbase + tid * 4);
    float rr[4] = {r4.x, r4.y, r4.z, r4.w};
    float v[4], mv[4];
#pragma unroll
    for (int u = 0; u < 4; u++) {
        mv[u] = maskAt(mask, mbase + tid * 4 + u, mode);
        msk[tid * 4 + u] = mv[u];
        v[u] = (mv[u] != 0.f) ? rr[u] : -1.0e4f;
    }
    float mx = bredMax(fmaxf(fmaxf(v[0], v[1]), fmaxf(v[2], v[3])), red);
    float e[4], s = 0.f;
#pragma unroll
    for (int u = 0; u < 4; u++) { e[u] = __expf(v[u] - mx); s += e[u]; }
    float tot = bredSum(s, red);
    const float l1v = *l1p;
    const float w0 = 1.f - l1v;
    float li = l1v / tot;
#pragma unroll
    for (int u = 0; u < 4; u++) relp[tid * 4 + u] = e[u] * li;
    __syncthreads();

    // ---- per-head: mask + softmax + blend ----
    for (int h = 0; h < HH; h++) {
        float* row = prob + (((long)(b * HH + h) * SS) + q) * SS;
        float4 s4 = *(const float4*)(row + tid * 4);
        float sv[4] = {s4.x, s4.y, s4.z, s4.w};
#pragma unroll
        for (int u = 0; u < 4; u++)
            if (msk[tid * 4 + u] != 0.f) sv[u] = -1.0e9f;
        float hm = bredMax(fmaxf(fmaxf(sv[0], sv[1]), fmaxf(sv[2], sv[3])), red);
        float he[4], hs = 0.f;
#pragma unroll
        for (int u = 0; u < 4; u++) { he[u] = __expf(sv[u] - hm); hs += he[u]; }
        float htot = bredSum(hs, red);
        float wi = w0 / htot;
        float4 o4;
        o4.x = he[0] * wi + relp[tid * 4 + 0];
        o4.y = he[1] * wi + relp[tid * 4 + 1];
        o4.z = he[2] * wi + relp[tid * 4 + 2];
        o4.w = he[3] * wi + relp[tid * 4 + 3];
        *(float4*)(row + tid * 4) = o4;
    }
}

// ---------------------------------------------------------------------------
// PV GEMM: out[bh,q,:] = P[bh,q,:] @ V[bh,:,:].  M=1024 per bh, N=64, K=1024.
// Tile 128(q) x 64(n), k-chunks of 64. micro 8x4 (as 8x2 pairs).
// Dyn smem 51200 B.
// ---------------------------------------------------------------------------
#define PV_SMEM ((64 * 132 + 64 * 68) * 4)

__global__ __launch_bounds__(256, 2) void pv_kernel(
    const float* __restrict__ prob, float* __restrict__ out0)
{
    extern __shared__ float sm[];
    float* Ps = sm;              // [64][132]  (k-major: Ps[k][m])
    float* Vs = sm + 64 * 132;   // [64][68]

    const int tid = threadIdx.x;
    const int tx = tid & 15, ty = tid >> 4;
    const int bh = blockIdx.y;
    const int q0 = blockIdx.x * 128;
    const int b = bh / HH, h = bh - b * HH;

    const float* pbase = prob + ((long)bh * SS + q0) * SS;
    const float* vbase = g_v + (long)bh * SS * HD;

    ull acc[8][2];
#pragma unroll
    for (int i = 0; i < 8; i++) { acc[i][0] = 0ull; acc[i][1] = 0ull; }

    for (int kc = 0; kc < 16; kc++) {
        __syncthreads();
        {   // P chunk: 128 q-rows x 64 k, transposed into Ps[k][m]
            int m = tid >> 1, half = tid & 1;
            const float* g = pbase + (long)m * SS + kc * 64 + half * 32;
#pragma unroll
            for (int i = 0; i < 8; i++) {
                float4 v = *(const float4*)(g + i * 4);
                int k = half * 32 + i * 4;
                Ps[(k + 0) * 132 + m] = v.x; Ps[(k + 1) * 132 + m] = v.y;
                Ps[(k + 2) * 132 + m] = v.z; Ps[(k + 3) * 132 + m] = v.w;
            }
        }
        {   // V chunk: 64 k-rows x 64 n
            int row = tid >> 2, c0 = (tid & 3) * 16;
            const float* g = vbase + (long)(kc * 64 + row) * HD + c0;
            float* p = Vs + row * 68 + c0;
#pragma unroll
            for (int i = 0; i < 4; i++)
                *(float4*)(p + i * 4) = *(const float4*)(g + i * 4);
        }
        __syncthreads();

#pragma unroll 4
        for (int k = 0; k < 64; k++) {
            const float* pr = Ps + k * 132;
            float4 a0 = *(const float4*)(pr + ty * 8);
            float4 a1 = *(const float4*)(pr + ty * 8 + 4);
            ulonglong2 bp = *(const ulonglong2*)(Vs + k * 68 + tx * 4);
            float a[8] = {a0.x, a0.y, a0.z, a0.w, a1.x, a1.y, a1.z, a1.w};
#pragma unroll
            for (int i = 0; i < 8; i++) {
                ull ai = pk2(a[i]);
                fma2(acc[i][0], ai, bp.x);
                fma2(acc[i][1], ai, bp.y);
            }
        }
    }

#pragma unroll
    for (int i = 0; i < 8; i++) {
        float2 lo = up2(acc[i][0]), hi = up2(acc[i][1]);
        *(float4*)(out0 + ((long)(b * SS) + q0 + ty * 8 + i) * DD + h * HD + tx * 4) =
            make_float4(lo.x, lo.y, hi.x, hi.y);
    }
}

// ---------------------------------------------------------------------------
extern "C" void kernel_launch(void* const* d_in, const int* in_sizes, int n_in,
                              void* d_out, int out_size)
{
    const float* query = (const float*)d_in[0];
    const float* key_t = (const float*)d_in[1];
    const float* value = (const float*)d_in[2];
    const float* rel   = (const float*)d_in[3];
    const void*  mask  = d_in[4];
    const float* l1    = (const float*)d_in[5];
    const float* Wq = (const float*)d_in[6];
    const float* bq = (const float*)d_in[7];
    const float* Wk = (const float*)d_in[8];
    const float* bk = (const float*)d_in[9];
    const float* Wv = (const float*)d_in[10];
    const float* bv = (const float*)d_in[11];

    float* out0 = (float*)d_out;                        // (B,S,D)
    float* prob = out0 + (long)BB * SS * DD;            // (B,H,S,S) — scores scratch, then prob

    cudaFuncSetAttribute(score_kernel,
                         cudaFuncAttributeMaxDynamicSharedMemorySize, SC_SMEM);
    cudaFuncSetAttribute(pv_kernel,
                         cudaFuncAttributeMaxDynamicSharedMemorySize, PV_SMEM);

    detect_mask_kernel<<<1, 256>>>((const unsigned char*)mask);

    dim3 pgrid(DD / 64, (BB * SS) / 128);
    proj_kernel<<<pgrid, 256>>>(query, Wq, bq, 0);
    proj_kernel<<<pgrid, 256>>>(key_t, Wk, bk, 1);
    proj_kernel<<<pgrid, 256>>>(value, Wv, bv, 2);

    dim3 sgrid(SS / 128, SS / 128, BB * HH);
    score_kernel<<<sgrid, 256, SC_SMEM>>>(prob);

    dim3 smgrid(SS, BB);
    softmax_kernel<<<smgrid, 256>>>(rel, mask, l1, prob);

    dim3 vgrid(SS / 128, BB * HH);
    pv_kernel<<<vgrid, 256, PV_SMEM>>>(prob, out0);
}

// round 7
// speedup vs baseline: 1.6293x; 1.3599x over previous
#include <cuda_runtime.h>
#include <cuda_bf16.h>

// Problem constants
#define BB 8
#define SS 1024
#define DD 768
#define HH 12
#define HD 64

// Scratch (no cudaMalloc allowed)
__device__ float g_q[BB * HH * SS * HD];     // (B,H,S,HD)
__device__ float g_k[BB * HH * SS * HD];
__device__ float g_v[BB * HH * SS * HD];
__device__ int   g_mask_mode;                // 0=f32, 1=i32, 2=u8

// ---------------------------------------------------------------------------
// Mask dtype detection: jax bool mask may be serialized as f32 / i32 / u8.
// ---------------------------------------------------------------------------
__global__ void detect_mask_kernel(const unsigned char* __restrict__ m) {
    __shared__ int f32flag, nz123;
    if (threadIdx.x == 0) { f32flag = 0; nz123 = 0; }
    __syncthreads();
    for (int i = threadIdx.x; i < 65536; i += blockDim.x) {
        unsigned char v = m[i];
        if (v) {
            int r = i & 3;
            if ((r == 3 && v == 0x3F) || (r == 2 && v == 0x80)) atomicOr(&f32flag, 1);
            if (r != 0) atomicOr(&nz123, 1);
        }
    }
    __syncthreads();
    if (threadIdx.x == 0)
        g_mask_mode = f32flag ? 0 : (nz123 ? 2 : 1);
}

__device__ __forceinline__ float maskAt(const void* m, long i, int mode) {
    if (mode == 0) return ((const float*)m)[i];
    if (mode == 1) return (float)((const int*)m)[i];
    return (float)((const unsigned char*)m)[i];
}

// ---------------------------------------------------------------------------
// Projection GEMM: Y = X @ W^T + bias, scattered to (B,H,S,HD).
// M=8192, N=768, K=768. Tile 256x64, micro 8x8 (32 row-groups x 8 col-groups).
// Per inner step: 4x LDS.128 (64B) vs 64 FFMA -> balanced pipes.
// ---------------------------------------------------------------------------
__global__ __launch_bounds__(256, 2) void proj_kernel(
    const float* __restrict__ X, const float* __restrict__ W,
    const float* __restrict__ bias, int which)
{
    __shared__ float As[16][264];  // [kk][m], k-major
    __shared__ float Bs[16][68];   // [kk][n]

    float* dst = (which == 0) ? g_q : (which == 1) ? g_k : g_v;

    const int tid = threadIdx.x;
    const int tx = tid & 7;        // 8 col-groups of 8
    const int ty = tid >> 3;       // 32 row-groups of 8
    const int m0 = blockIdx.y * 256;
    const int n0 = blockIdx.x * 64;

    float acc[8][8];
#pragma unroll
    for (int i = 0; i < 8; i++)
#pragma unroll
        for (int j = 0; j < 8; j++) acc[i][j] = 0.f;

    for (int k0 = 0; k0 < DD; k0 += 16) {
        {   // A: row m = tid reads 16 k-values, transpose into As[k][m]
            const float* g = X + (long)(m0 + tid) * DD + k0;
#pragma unroll
            for (int i = 0; i < 4; i++) {
                float4 v = *(const float4*)(g + i * 4);
                As[i * 4 + 0][tid] = v.x; As[i * 4 + 1][tid] = v.y;
                As[i * 4 + 2][tid] = v.z; As[i * 4 + 3][tid] = v.w;
            }
        }
        {   // B: 64 rows x 16 k
            int n = tid >> 2;
            int kq = tid & 3;
            float4 bv = *(const float4*)(W + (long)(n0 + n) * DD + k0 + kq * 4);
            Bs[kq * 4 + 0][n] = bv.x; Bs[kq * 4 + 1][n] = bv.y;
            Bs[kq * 4 + 2][n] = bv.z; Bs[kq * 4 + 3][n] = bv.w;
        }
        __syncthreads();
#pragma unroll
        for (int kk = 0; kk < 16; kk++) {
            float4 a0 = *(const float4*)(&As[kk][ty * 8]);
            float4 a1 = *(const float4*)(&As[kk][ty * 8 + 4]);
            float4 b0 = *(const float4*)(&Bs[kk][tx * 8]);
            float4 b1 = *(const float4*)(&Bs[kk][tx * 8 + 4]);
            float a[8] = {a0.x, a0.y, a0.z, a0.w, a1.x, a1.y, a1.z, a1.w};
            float b[8] = {b0.x, b0.y, b0.z, b0.w, b1.x, b1.y, b1.z, b1.w};
#pragma unroll
            for (int i = 0; i < 8; i++)
#pragma unroll
                for (int j = 0; j < 8; j++)
                    acc[i][j] += a[i] * b[j];
        }
        __syncthreads();
    }

    float4 bb0 = *(const float4*)(bias + n0 + tx * 8);
    float4 bb1 = *(const float4*)(bias + n0 + tx * 8 + 4);
    int h = blockIdx.x;  // n0 = h*64, NT==HD
#pragma unroll
    for (int i = 0; i < 8; i++) {
        int m = m0 + ty * 8 + i;
        int b = m >> 10, s = m & 1023;
        float* p = dst + (((long)(b * HH + h) << 10) + s) * HD + tx * 8;
        *(float4*)p = make_float4(acc[i][0] + bb0.x, acc[i][1] + bb0.y,
                                  acc[i][2] + bb0.z, acc[i][3] + bb0.w);
        *(float4*)(p + 4) = make_float4(acc[i][4] + bb1.x, acc[i][5] + bb1.y,
                                        acc[i][6] + bb1.z, acc[i][7] + bb1.w);
    }
}

// ---------------------------------------------------------------------------
// Scores GEMM: S[bh,q,k] = (Q K^T) / 8, raw (unmasked), written to prob
// region as scratch. Tile 128(q) x 128(k), K-depth 64 loaded once.
// micro 8x8: per d-step 4x LDS.128 vs 64 FFMA -> balanced.
// ---------------------------------------------------------------------------
#define SC_SMEM (2 * 64 * 132 * 4)

__global__ __launch_bounds__(256, 2) void score_kernel(float* __restrict__ prob)
{
    extern __shared__ float sm[];
    float* Qs = sm;              // [64][132]  (d-major: Qs[d][m])
    float* Ks = sm + 64 * 132;   // [64][132]

    const int tid = threadIdx.x;
    const int tx = tid & 15;     // 16 col-groups of 8 -> 128 cols
    const int ty = tid >> 4;     // 16 row-groups of 8 -> 128 rows
    const int bh = blockIdx.z;
    const int q0 = blockIdx.y * 128, k0 = blockIdx.x * 128;

    const float* qbase = g_q + ((long)bh * SS + q0) * HD;
    const float* kbase = g_k + ((long)bh * SS + k0) * HD;

    {   // load + transpose both tiles: 128 rows x 64 d each
        int m = tid >> 1, half = tid & 1;
        const float* gq = qbase + m * HD + half * 32;
        const float* gk = kbase + m * HD + half * 32;
#pragma unroll
        for (int i = 0; i < 8; i++) {
            float4 v = *(const float4*)(gq + i * 4);
            int d = half * 32 + i * 4;
            Qs[(d + 0) * 132 + m] = v.x; Qs[(d + 1) * 132 + m] = v.y;
            Qs[(d + 2) * 132 + m] = v.z; Qs[(d + 3) * 132 + m] = v.w;
            float4 w = *(const float4*)(gk + i * 4);
            Ks[(d + 0) * 132 + m] = w.x; Ks[(d + 1) * 132 + m] = w.y;
            Ks[(d + 2) * 132 + m] = w.z; Ks[(d + 3) * 132 + m] = w.w;
        }
    }
    __syncthreads();

    float acc[8][8];
#pragma unroll
    for (int i = 0; i < 8; i++)
#pragma unroll
        for (int j = 0; j < 8; j++) acc[i][j] = 0.f;

#pragma unroll 4
    for (int d = 0; d < 64; d++) {
        const float* qr = Qs + d * 132;
        const float* kr = Ks + d * 132;
        float4 a0 = *(const float4*)(qr + ty * 8);
        float4 a1 = *(const float4*)(qr + ty * 8 + 4);
        float4 b0 = *(const float4*)(kr + tx * 8);
        float4 b1 = *(const float4*)(kr + tx * 8 + 4);
        float a[8] = {a0.x, a0.y, a0.z, a0.w, a1.x, a1.y, a1.z, a1.w};
        float b[8] = {b0.x, b0.y, b0.z, b0.w, b1.x, b1.y, b1.z, b1.w};
#pragma unroll
        for (int i = 0; i < 8; i++)
#pragma unroll
            for (int j = 0; j < 8; j++)
                acc[i][j] += a[i] * b[j];
    }

#pragma unroll
    for (int i = 0; i < 8; i++) {
        long row = ((long)bh * SS + q0 + ty * 8 + i) * SS;
        *(float4*)(prob + row + k0 + tx * 8) =
            make_float4(acc[i][0] * 0.125f, acc[i][1] * 0.125f,
                        acc[i][2] * 0.125f, acc[i][3] * 0.125f);
        *(float4*)(prob + row + k0 + tx * 8 + 4) =
            make_float4(acc[i][4] * 0.125f, acc[i][5] * 0.125f,
                        acc[i][6] * 0.125f, acc[i][7] * 0.125f);
    }
}

// ---------------------------------------------------------------------------
// Softmax + mask + rel-blend, in place on prob region.
// Block = (q, b); computes rel_attn ONCE per (b,q), then loops 12 heads.
// ---------------------------------------------------------------------------
__device__ __forceinline__ float bredMax(float v, volatile float* red) {
#pragma unroll
    for (int o = 16; o; o >>= 1) v = fmaxf(v, __shfl_xor_sync(0xffffffffu, v, o));
    if ((threadIdx.x & 31) == 0) red[threadIdx.x >> 5] = v;
    __syncthreads();
    float r = red[0];
#pragma unroll
    for (int i = 1; i < 8; i++) r = fmaxf(r, red[i]);
    __syncthreads();
    return r;
}
__device__ __forceinline__ float bredSum(float v, volatile float* red) {
#pragma unroll
    for (int o = 16; o; o >>= 1) v += __shfl_xor_sync(0xffffffffu, v, o);
    if ((threadIdx.x & 31) == 0) red[threadIdx.x >> 5] = v;
    __syncthreads();
    float r = 0.f;
#pragma unroll
    for (int i = 0; i < 8; i++) r += red[i];
    __syncthreads();
    return r;
}

__global__ __launch_bounds__(256) void softmax_kernel(
    const float* __restrict__ rel, const void* __restrict__ mask,
    const float* __restrict__ l1p, float* __restrict__ prob)
{
    __shared__ float relp[1024];   // l1 * rel_attn
    __shared__ float msk[1024];
    __shared__ float red[8];

    const int b = blockIdx.y, q = blockIdx.x, tid = threadIdx.x;
    const int mode = g_mask_mode;
    const long mbase = ((long)(b * SS + q)) * SS;

    // ---- rel_attn row (head-independent), computed once ----
    float4 r4 = *(const float4*)(rel + mbase + tid * 4);
    float rr[4] = {r4.x, r4.y, r4.z, r4.w};
    float v[4], mv[4];
#pragma unroll
    for (int u = 0; u < 4; u++) {
        mv[u] = maskAt(mask, mbase + tid * 4 + u, mode);
        msk[tid * 4 + u] = mv[u];
        v[u] = (mv[u] != 0.f) ? rr[u] : -1.0e4f;
    }
    float mx = bredMax(fmaxf(fmaxf(v[0], v[1]), fmaxf(v[2], v[3])), red);
    float e[4], s = 0.f;
#pragma unroll
    for (int u = 0; u < 4; u++) { e[u] = __expf(v[u] - mx); s += e[u]; }
    float tot = bredSum(s, red);
    const float l1v = *l1p;
    const float w0 = 1.f - l1v;
    float li = l1v / tot;
#pragma unroll
    for (int u = 0; u < 4; u++) relp[tid * 4 + u] = e[u] * li;
    __syncthreads();

    // ---- per-head: mask + softmax + blend ----
    for (int h = 0; h < HH; h++) {
        float* row = prob + (((long)(b * HH + h) * SS) + q) * SS;
        float4 s4 = *(const float4*)(row + tid * 4);
        float sv[4] = {s4.x, s4.y, s4.z, s4.w};
#pragma unroll
        for (int u = 0; u < 4; u++)
            if (msk[tid * 4 + u] != 0.f) sv[u] = -1.0e9f;
        float hm = bredMax(fmaxf(fmaxf(sv[0], sv[1]), fmaxf(sv[2], sv[3])), red);
        float he[4], hs = 0.f;
#pragma unroll
        for (int u = 0; u < 4; u++) { he[u] = __expf(sv[u] - hm); hs += he[u]; }
        float htot = bredSum(hs, red);
        float wi = w0 / htot;
        float4 o4;
        o4.x = he[0] * wi + relp[tid * 4 + 0];
        o4.y = he[1] * wi + relp[tid * 4 + 1];
        o4.z = he[2] * wi + relp[tid * 4 + 2];
        o4.w = he[3] * wi + relp[tid * 4 + 3];
        *(float4*)(row + tid * 4) = o4;
    }
}

// ---------------------------------------------------------------------------
// PV GEMM: out[bh,q,:] = P[bh,q,:] @ V[bh,:,:].  M=1024 per bh, N=64, K=1024.
// Tile 256(q) x 64(n), k-chunks of 64. micro 8x8 -> balanced LDS/FMA.
// Dyn smem 83968 B.
// ---------------------------------------------------------------------------
#define PV_SMEM ((64 * 260 + 64 * 68) * 4)

__global__ __launch_bounds__(256, 1) void pv_kernel(
    const float* __restrict__ prob, float* __restrict__ out0)
{
    extern __shared__ float sm[];
    float* Ps = sm;              // [64][260]  (k-major: Ps[k][m])
    float* Vs = sm + 64 * 260;   // [64][68]

    const int tid = threadIdx.x;
    const int tx = tid & 7;      // 8 col-groups of 8 -> 64 cols
    const int ty = tid >> 3;     // 32 row-groups of 8 -> 256 rows
    const int bh = blockIdx.y;
    const int q0 = blockIdx.x * 256;
    const int b = bh / HH, h = bh - b * HH;

    const float* pbase = prob + ((long)bh * SS + q0) * SS;
    const float* vbase = g_v + (long)bh * SS * HD;

    float acc[8][8];
#pragma unroll
    for (int i = 0; i < 8; i++)
#pragma unroll
        for (int j = 0; j < 8; j++) acc[i][j] = 0.f;

    for (int kc = 0; kc < 16; kc++) {
        __syncthreads();
        {   // P chunk: 256 q-rows x 64 k; thread t owns row t, transposes
            const float* g = pbase + (long)tid * SS + kc * 64;
#pragma unroll
            for (int i = 0; i < 16; i++) {
                float4 v = *(const float4*)(g + i * 4);
                int k = i * 4;
                Ps[(k + 0) * 260 + tid] = v.x; Ps[(k + 1) * 260 + tid] = v.y;
                Ps[(k + 2) * 260 + tid] = v.z; Ps[(k + 3) * 260 + tid] = v.w;
            }
        }
        {   // V chunk: 64 k-rows x 64 n
            int row = tid >> 2, c0 = (tid & 3) * 16;
            const float* g = vbase + (long)(kc * 64 + row) * HD + c0;
            float* p = Vs + row * 68 + c0;
#pragma unroll
            for (int i = 0; i < 4; i++)
                *(float4*)(p + i * 4) = *(const float4*)(g + i * 4);
        }
        __syncthreads();

#pragma unroll 4
        for (int k = 0; k < 64; k++) {
            const float* pr = Ps + k * 260;
            const float* vr = Vs + k * 68;
            float4 a0 = *(const float4*)(pr + ty * 8);
            float4 a1 = *(const float4*)(pr + ty * 8 + 4);
            float4 b0 = *(const float4*)(vr + tx * 8);
            float4 b1 = *(const float4*)(vr + tx * 8 + 4);
            float a[8] = {a0.x, a0.y, a0.z, a0.w, a1.x, a1.y, a1.z, a1.w};
            float bb[8] = {b0.x, b0.y, b0.z, b0.w, b1.x, b1.y, b1.z, b1.w};
#pragma unroll
            for (int i = 0; i < 8; i++)
#pragma unroll
                for (int j = 0; j < 8; j++)
                    acc[i][j] += a[i] * bb[j];
        }
    }

#pragma unroll
    for (int i = 0; i < 8; i++) {
        float* p = out0 + ((long)(b * SS) + q0 + ty * 8 + i) * DD + h * HD + tx * 8;
        *(float4*)p = make_float4(acc[i][0], acc[i][1], acc[i][2], acc[i][3]);
        *(float4*)(p + 4) = make_float4(acc[i][4], acc[i][5], acc[i][6], acc[i][7]);
    }
}

// ---------------------------------------------------------------------------
extern "C" void kernel_launch(void* const* d_in, const int* in_sizes, int n_in,
                              void* d_out, int out_size)
{
    const float* query = (const float*)d_in[0];
    const float* key_t = (const float*)d_in[1];
    const float* value = (const float*)d_in[2];
    const float* rel   = (const float*)d_in[3];
    const void*  mask  = d_in[4];
    const float* l1    = (const float*)d_in[5];
    const float* Wq = (const float*)d_in[6];
    const float* bq = (const float*)d_in[7];
    const float* Wk = (const float*)d_in[8];
    const float* bk = (const float*)d_in[9];
    const float* Wv = (const float*)d_in[10];
    const float* bv = (const float*)d_in[11];

    float* out0 = (float*)d_out;                        // (B,S,D)
    float* prob = out0 + (long)BB * SS * DD;            // (B,H,S,S) — scores scratch, then prob

    cudaFuncSetAttribute(score_kernel,
                         cudaFuncAttributeMaxDynamicSharedMemorySize, SC_SMEM);
    cudaFuncSetAttribute(pv_kernel,
                         cudaFuncAttributeMaxDynamicSharedMemorySize, PV_SMEM);

    detect_mask_kernel<<<1, 256>>>((const unsigned char*)mask);

    dim3 pgrid(DD / 64, (BB * SS) / 256);
    proj_kernel<<<pgrid, 256>>>(query, Wq, bq, 0);
    proj_kernel<<<pgrid, 256>>>(key_t, Wk, bk, 1);
    proj_kernel<<<pgrid, 256>>>(value, Wv, bv, 2);

    dim3 sgrid(SS / 128, SS / 128, BB * HH);
    score_kernel<<<sgrid, 256, SC_SMEM>>>(prob);

    dim3 smgrid(SS, BB);
    softmax_kernel<<<smgrid, 256>>>(rel, mask, l1, prob);

    dim3 vgrid(SS / 256, BB * HH);
    pv_kernel<<<vgrid, 256, PV_SMEM>>>(prob, out0);
}

// round 9
// speedup vs baseline: 3.0862x; 1.8942x over previous
#include <cuda_runtime.h>
#include <cuda_bf16.h>

// Problem constants
#define BB 8
#define SS 1024
#define DD 768
#define HH 12
#define HD 64
#define NBH (BB * HH)

// Scratch (no cudaMalloc allowed) — bf16 hi/lo split operands, natural layouts
__device__ __nv_bfloat16 g_qh[NBH * SS * HD];   // (bh, s, d)
__device__ __nv_bfloat16 g_ql[NBH * SS * HD];
__device__ __nv_bfloat16 g_kh[NBH * SS * HD];
__device__ __nv_bfloat16 g_kl[NBH * SS * HD];
__device__ __nv_bfloat16 g_vh[NBH * SS * HD];
__device__ __nv_bfloat16 g_vl[NBH * SS * HD];
__device__ int g_mask_mode;                     // 0=f32, 1=i32, 2=u8

// ---------------------------------------------------------------------------
// Warp-MMA helpers (baseline PTX, no 'a'-gated features)
// ---------------------------------------------------------------------------
__device__ __forceinline__ unsigned smem_u32(const void* p) {
    unsigned a;
    asm("{ .reg .u64 t; cvta.to.shared.u64 t, %1; cvt.u32.u64 %0, t; }"
        : "=r"(a) : "l"(p));
    return a;
}
__device__ __forceinline__ void ldsm4(unsigned r[4], unsigned a) {
    asm volatile("ldmatrix.sync.aligned.m8n8.x4.shared.b16 {%0,%1,%2,%3}, [%4];"
                 : "=r"(r[0]), "=r"(r[1]), "=r"(r[2]), "=r"(r[3]) : "r"(a));
}
__device__ __forceinline__ void ldsm4t(unsigned r[4], unsigned a) {
    asm volatile("ldmatrix.sync.aligned.m8n8.x4.trans.shared.b16 {%0,%1,%2,%3}, [%4];"
                 : "=r"(r[0]), "=r"(r[1]), "=r"(r[2]), "=r"(r[3]) : "r"(a));
}
__device__ __forceinline__ void mmabf(float c[4], const unsigned a[4],
                                      unsigned b0, unsigned b1) {
    asm volatile("mma.sync.aligned.m16n8k16.row.col.f32.bf16.bf16.f32 "
                 "{%0,%1,%2,%3}, {%4,%5,%6,%7}, {%8,%9}, {%0,%1,%2,%3};"
                 : "+f"(c[0]), "+f"(c[1]), "+f"(c[2]), "+f"(c[3])
                 : "r"(a[0]), "r"(a[1]), "r"(a[2]), "r"(a[3]), "r"(b0), "r"(b1));
}

// split fp32 pair -> two packed-bf16 words (hi pair, lo pair)
__device__ __forceinline__ void split_pair(float a, float b, unsigned& hi, unsigned& lo) {
    __nv_bfloat162 h2 = __floats2bfloat162_rn(a, b);
    float ra = a - __bfloat162float(h2.x);
    float rb = b - __bfloat162float(h2.y);
    __nv_bfloat162 l2 = __floats2bfloat162_rn(ra, rb);
    hi = *(unsigned*)&h2;
    lo = *(unsigned*)&l2;
}

// padded smem row: 72 bf16 (144 B) -> LDSM rows land on distinct 16B banks
#define PAD 72
#define ROWB 144

// ---------------------------------------------------------------------------
// Mask dtype detection
// ---------------------------------------------------------------------------
__global__ void detect_mask_kernel(const unsigned char* __restrict__ m) {
    __shared__ int f32flag, nz123;
    if (threadIdx.x == 0) { f32flag = 0; nz123 = 0; }
    __syncthreads();
    for (int i = threadIdx.x; i < 65536; i += blockDim.x) {
        unsigned char v = m[i];
        if (v) {
            int r = i & 3;
            if ((r == 3 && v == 0x3F) || (r == 2 && v == 0x80)) atomicOr(&f32flag, 1);
            if (r != 0) atomicOr(&nz123, 1);
        }
    }
    __syncthreads();
    if (threadIdx.x == 0)
        g_mask_mode = f32flag ? 0 : (nz123 ? 2 : 1);
}

__device__ __forceinline__ float maskAt(const void* m, long i, int mode) {
    if (mode == 0) return ((const float*)m)[i];
    if (mode == 1) return (float)((const int*)m)[i];
    return (float)((const unsigned char*)m)[i];
}

// ---------------------------------------------------------------------------
// Projection (HMMA): Y = X @ W^T + bias -> bf16 hi/lo splits [bh][s][d].
// Block 256 thr = 8 warps (4m x 2n); tile 128m x 64n; K=768 in 12 chunks of 64.
// smem: bias(256B) + Ah/Al[128][72] + Bh/Bl[64][72] = 55552 B.
// ---------------------------------------------------------------------------
#define PJ_BIAS 0
#define PJ_AH 256
#define PJ_AL (PJ_AH + 128 * ROWB)
#define PJ_BH (PJ_AL + 128 * ROWB)
#define PJ_BL (PJ_BH + 64 * ROWB)
#define PJ_SMEM (PJ_BL + 64 * ROWB)

__global__ __launch_bounds__(256, 2) void proj_kernel(
    const float* __restrict__ X, const float* __restrict__ W,
    const float* __restrict__ bias, int which)
{
    extern __shared__ char dynsm[];
    const unsigned sbase = smem_u32(dynsm);
    const int tid = threadIdx.x;
    const int lane = tid & 31, warp = tid >> 5;
    const int wm = warp & 3, wn = warp >> 2;     // 4m x 2n
    const int h = blockIdx.x;
    const int m0 = blockIdx.y * 128;
    const int n0 = h * HD;

    float* biasSm = (float*)(dynsm + PJ_BIAS);
    if (tid < 64) biasSm[tid] = bias[n0 + tid];

    float acc[2][4][4];
#pragma unroll
    for (int i = 0; i < 2; i++)
#pragma unroll
        for (int j = 0; j < 4; j++)
#pragma unroll
            for (int u = 0; u < 4; u++) acc[i][j][u] = 0.f;

    const int o8 = lane >> 3;
    const unsigned a_off = ((wm * 32 + (lane & 15)) * PAD + (lane >> 4) * 8) * 2;
    const unsigned b_off = ((wn * 32 + (lane & 7) + (o8 >> 1) * 8) * PAD + (o8 & 1) * 8) * 2;

    for (int c = 0; c < 12; c++) {
        __syncthreads();
        {   // stage X chunk: 128 rows x 64 k fp32 -> split
            int row = tid >> 1, kh = (tid & 1) * 32;
            const float* g = X + (long)(m0 + row) * DD + c * 64 + kh;
#pragma unroll
            for (int i = 0; i < 8; i++) {
                float4 v = *(const float4*)(g + i * 4);
                unsigned h0, l0, h1, l1;
                split_pair(v.x, v.y, h0, l0);
                split_pair(v.z, v.w, h1, l1);
                unsigned o = (row * PAD + kh + i * 4) * 2;
                *(unsigned*)(dynsm + PJ_AH + o) = h0;
                *(unsigned*)(dynsm + PJ_AH + o + 4) = h1;
                *(unsigned*)(dynsm + PJ_AL + o) = l0;
                *(unsigned*)(dynsm + PJ_AL + o + 4) = l1;
            }
        }
        {   // stage W chunk: 64 rows x 64 k fp32 -> split
            int n = tid >> 2, kq = (tid & 3) * 16;
            const float* g = W + (long)(n0 + n) * DD + c * 64 + kq;
#pragma unroll
            for (int i = 0; i < 4; i++) {
                float4 v = *(const float4*)(g + i * 4);
                unsigned h0, l0, h1, l1;
                split_pair(v.x, v.y, h0, l0);
                split_pair(v.z, v.w, h1, l1);
                unsigned o = (n * PAD + kq + i * 4) * 2;
                *(unsigned*)(dynsm + PJ_BH + o) = h0;
                *(unsigned*)(dynsm + PJ_BH + o + 4) = h1;
                *(unsigned*)(dynsm + PJ_BL + o) = l0;
                *(unsigned*)(dynsm + PJ_BL + o + 4) = l1;
            }
        }
        __syncthreads();

#pragma unroll
        for (int kk = 0; kk < 64; kk += 16) {
            unsigned Ah[2][4], Al[2][4], B[2][4];
            ldsm4(Ah[0], sbase + PJ_AH + a_off + kk * 2);
            ldsm4(Ah[1], sbase + PJ_AH + a_off + kk * 2 + 16 * ROWB);
            ldsm4(Al[0], sbase + PJ_AL + a_off + kk * 2);
            ldsm4(Al[1], sbase + PJ_AL + a_off + kk * 2 + 16 * ROWB);
            ldsm4(B[0], sbase + PJ_BH + b_off + kk * 2);
            ldsm4(B[1], sbase + PJ_BH + b_off + kk * 2 + 16 * ROWB);
#pragma unroll
            for (int mi = 0; mi < 2; mi++)
#pragma unroll
                for (int j = 0; j < 2; j++) {
                    mmabf(acc[mi][2 * j], Ah[mi], B[j][0], B[j][1]);
                    mmabf(acc[mi][2 * j + 1], Ah[mi], B[j][2], B[j][3]);
                }
#pragma unroll
            for (int mi = 0; mi < 2; mi++)
#pragma unroll
                for (int j = 0; j < 2; j++) {
                    mmabf(acc[mi][2 * j], Al[mi], B[j][0], B[j][1]);
                    mmabf(acc[mi][2 * j + 1], Al[mi], B[j][2], B[j][3]);
                }
            ldsm4(B[0], sbase + PJ_BL + b_off + kk * 2);
            ldsm4(B[1], sbase + PJ_BL + b_off + kk * 2 + 16 * ROWB);
#pragma unroll
            for (int mi = 0; mi < 2; mi++)
#pragma unroll
                for (int j = 0; j < 2; j++) {
                    mmabf(acc[mi][2 * j], Ah[mi], B[j][0], B[j][1]);
                    mmabf(acc[mi][2 * j + 1], Ah[mi], B[j][2], B[j][3]);
                }
        }
    }

    __nv_bfloat16* dh = (which == 0) ? g_qh : (which == 1) ? g_kh : g_vh;
    __nv_bfloat16* dl = (which == 0) ? g_ql : (which == 1) ? g_kl : g_vl;
    const int r0 = lane >> 2, cp = (lane & 3) * 2;
#pragma unroll
    for (int mi = 0; mi < 2; mi++)
#pragma unroll
        for (int j2 = 0; j2 < 4; j2++) {
            int d = wn * 32 + j2 * 8 + cp;
            float b0v = biasSm[d], b1v = biasSm[d + 1];
#pragma unroll
            for (int half = 0; half < 2; half++) {
                int m = m0 + wm * 32 + mi * 16 + r0 + half * 8;
                int b = m >> 10, s = m & 1023;
                long bh = (long)(b * HH + h);
                float y0 = acc[mi][j2][half * 2] + b0v;
                float y1 = acc[mi][j2][half * 2 + 1] + b1v;
                unsigned hv, lv;
                split_pair(y0, y1, hv, lv);
                long base = (bh * SS + s) * HD + d;
                *(unsigned*)(dh + base) = hv;
                *(unsigned*)(dl + base) = lv;
            }
        }
}

// ---------------------------------------------------------------------------
// Scores (HMMA): S = (Q K^T)/8 -> prob region (fp32 scratch).
// Block 256 thr = 8 warps (4m x 2n), tile 128q x 128k, warp 32q x 64k, K=64.
// smem: Qh/Ql/Kh/Kl [128][72] bf16 = 73728 B.
// ---------------------------------------------------------------------------
#define SC_QH 0
#define SC_QL (SC_QH + 128 * ROWB)
#define SC_KH (SC_QL + 128 * ROWB)
#define SC_KL (SC_KH + 128 * ROWB)
#define SC_SMEM (SC_KL + 128 * ROWB)

__global__ __launch_bounds__(256, 2) void score_kernel(float* __restrict__ prob)
{
    extern __shared__ char dynsm[];
    const unsigned sbase = smem_u32(dynsm);
    const int tid = threadIdx.x;
    const int lane = tid & 31, warp = tid >> 5;
    const int wm = warp & 3, wn = warp >> 2;
    const int bh = blockIdx.z;
    const int q0 = blockIdx.y * 128, k0 = blockIdx.x * 128;

    {   // stage 4 bf16 tiles: 128 rows x 64 d each
        int row = tid >> 1, hd0 = (tid & 1) * 32;
        long qrow = ((long)bh * SS + q0 + row) * HD + hd0;
        long krow = ((long)bh * SS + k0 + row) * HD + hd0;
        unsigned so = (row * PAD + hd0) * 2;
#pragma unroll
        for (int i = 0; i < 4; i++) {
            *(float4*)(dynsm + SC_QH + so + i * 16) = *(const float4*)(g_qh + qrow + i * 8);
            *(float4*)(dynsm + SC_QL + so + i * 16) = *(const float4*)(g_ql + qrow + i * 8);
            *(float4*)(dynsm + SC_KH + so + i * 16) = *(const float4*)(g_kh + krow + i * 8);
            *(float4*)(dynsm + SC_KL + so + i * 16) = *(const float4*)(g_kl + krow + i * 8);
        }
    }
    __syncthreads();

    float acc[2][8][4];
#pragma unroll
    for (int i = 0; i < 2; i++)
#pragma unroll
        for (int j = 0; j < 8; j++)
#pragma unroll
            for (int u = 0; u < 4; u++) acc[i][j][u] = 0.f;

    const int o8 = lane >> 3;
    const unsigned a_off = ((wm * 32 + (lane & 15)) * PAD + (lane >> 4) * 8) * 2;
    const unsigned b_off = ((wn * 64 + (lane & 7) + (o8 >> 1) * 8) * PAD + (o8 & 1) * 8) * 2;

#pragma unroll
    for (int kk = 0; kk < 64; kk += 16) {
        unsigned Ah[2][4], Al[2][4], B[4][4];
        ldsm4(Ah[0], sbase + SC_QH + a_off + kk * 2);
        ldsm4(Ah[1], sbase + SC_QH + a_off + kk * 2 + 16 * ROWB);
        ldsm4(Al[0], sbase + SC_QL + a_off + kk * 2);
        ldsm4(Al[1], sbase + SC_QL + a_off + kk * 2 + 16 * ROWB);
#pragma unroll
        for (int j = 0; j < 4; j++)
            ldsm4(B[j], sbase + SC_KH + b_off + kk * 2 + j * 16 * ROWB);
#pragma unroll
        for (int mi = 0; mi < 2; mi++)
#pragma unroll
            for (int j = 0; j < 4; j++) {
                mmabf(acc[mi][2 * j], Ah[mi], B[j][0], B[j][1]);
                mmabf(acc[mi][2 * j + 1], Ah[mi], B[j][2], B[j][3]);
            }
#pragma unroll
        for (int mi = 0; mi < 2; mi++)
#pragma unroll
            for (int j = 0; j < 4; j++) {
                mmabf(acc[mi][2 * j], Al[mi], B[j][0], B[j][1]);
                mmabf(acc[mi][2 * j + 1], Al[mi], B[j][2], B[j][3]);
            }
#pragma unroll
        for (int j = 0; j < 4; j++)
            ldsm4(B[j], sbase + SC_KL + b_off + kk * 2 + j * 16 * ROWB);
#pragma unroll
        for (int mi = 0; mi < 2; mi++)
#pragma unroll
            for (int j = 0; j < 4; j++) {
                mmabf(acc[mi][2 * j], Ah[mi], B[j][0], B[j][1]);
                mmabf(acc[mi][2 * j + 1], Ah[mi], B[j][2], B[j][3]);
            }
    }

    const int r0 = lane >> 2, cp = (lane & 3) * 2;
#pragma unroll
    for (int mi = 0; mi < 2; mi++)
#pragma unroll
        for (int j = 0; j < 8; j++) {
            int k = k0 + wn * 64 + j * 8 + cp;
#pragma unroll
            for (int half = 0; half < 2; half++) {
                int q = q0 + wm * 32 + mi * 16 + r0 + half * 8;
                float2 o;
                o.x = acc[mi][j][half * 2] * 0.125f;
                o.y = acc[mi][j][half * 2 + 1] * 0.125f;
                *(float2*)(prob + ((long)bh * SS + q) * SS + k) = o;
            }
        }
}

// ---------------------------------------------------------------------------
// Softmax + mask + rel-blend, in place on prob (unchanged, proven).
// ---------------------------------------------------------------------------
__device__ __forceinline__ float bredMax(float v, volatile float* red) {
#pragma unroll
    for (int o = 16; o; o >>= 1) v = fmaxf(v, __shfl_xor_sync(0xffffffffu, v, o));
    if ((threadIdx.x & 31) == 0) red[threadIdx.x >> 5] = v;
    __syncthreads();
    float r = red[0];
#pragma unroll
    for (int i = 1; i < 8; i++) r = fmaxf(r, red[i]);
    __syncthreads();
    return r;
}
__device__ __forceinline__ float bredSum(float v, volatile float* red) {
#pragma unroll
    for (int o = 16; o; o >>= 1) v += __shfl_xor_sync(0xffffffffu, v, o);
    if ((threadIdx.x & 31) == 0) red[threadIdx.x >> 5] = v;
    __syncthreads();
    float r = 0.f;
#pragma unroll
    for (int i = 0; i < 8; i++) r += red[i];
    __syncthreads();
    return r;
}

__global__ __launch_bounds__(256) void softmax_kernel(
    const float* __restrict__ rel, const void* __restrict__ mask,
    const float* __restrict__ l1p, float* __restrict__ prob)
{
    __shared__ float relp[1024];
    __shared__ float msk[1024];
    __shared__ float red[8];

    const int b = blockIdx.y, q = blockIdx.x, tid = threadIdx.x;
    const int mode = g_mask_mode;
    const long mbase = ((long)(b * SS + q)) * SS;

    float4 r4 = *(const float4*)(rel + mbase + tid * 4);
    float rr[4] = {r4.x, r4.y, r4.z, r4.w};
    float v[4], mv[4];
#pragma unroll
    for (int u = 0; u < 4; u++) {
        mv[u] = maskAt(mask, mbase + tid * 4 + u, mode);
        msk[tid * 4 + u] = mv[u];
        v[u] = (mv[u] != 0.f) ? rr[u] : -1.0e4f;
    }
    float mx = bredMax(fmaxf(fmaxf(v[0], v[1]), fmaxf(v[2], v[3])), red);
    float e[4], s = 0.f;
#pragma unroll
    for (int u = 0; u < 4; u++) { e[u] = __expf(v[u] - mx); s += e[u]; }
    float tot = bredSum(s, red);
    const float l1v = *l1p;
    const float w0 = 1.f - l1v;
    float li = l1v / tot;
#pragma unroll
    for (int u = 0; u < 4; u++) relp[tid * 4 + u] = e[u] * li;
    __syncthreads();

    for (int h = 0; h < HH; h++) {
        float* row = prob + (((long)(b * HH + h) * SS) + q) * SS;
        float4 s4 = *(const float4*)(row + tid * 4);
        float sv[4] = {s4.x, s4.y, s4.z, s4.w};
#pragma unroll
        for (int u = 0; u < 4; u++)
            if (msk[tid * 4 + u] != 0.f) sv[u] = -1.0e9f;
        float hm = bredMax(fmaxf(fmaxf(sv[0], sv[1]), fmaxf(sv[2], sv[3])), red);
        float he[4], hs = 0.f;
#pragma unroll
        for (int u = 0; u < 4; u++) { he[u] = __expf(sv[u] - hm); hs += he[u]; }
        float htot = bredSum(hs, red);
        float wi = w0 / htot;
        float4 o4;
        o4.x = he[0] * wi + relp[tid * 4 + 0];
        o4.y = he[1] * wi + relp[tid * 4 + 1];
        o4.z = he[2] * wi + relp[tid * 4 + 2];
        o4.w = he[3] * wi + relp[tid * 4 + 3];
        *(float4*)(row + tid * 4) = o4;
    }
}

// ---------------------------------------------------------------------------
// PV (HMMA): out[bh,q,d] = sum_s P[q][s] * V[s][d].
// Block 256 thr = 8 warps (4m x 2n), tile 128q x 64d, K=1024 in 16 chunks.
// A = P split from fp32; B = V bf16 via ldmatrix.trans ([s][d] natural layout).
// smem: Ph/Pl[128][72] + Vh/Vl[64][72] = 55296 B.
// ---------------------------------------------------------------------------
#define PV_PH 0
#define PV_PL (PV_PH + 128 * ROWB)
#define PV_VH (PV_PL + 128 * ROWB)
#define PV_VL (PV_VH + 64 * ROWB)
#define PV_SMEM (PV_VL + 64 * ROWB)

__global__ __launch_bounds__(256, 2) void pv_kernel(
    const float* __restrict__ prob, float* __restrict__ out0)
{
    extern __shared__ char dynsm[];
    const unsigned sbase = smem_u32(dynsm);
    const int tid = threadIdx.x;
    const int lane = tid & 31, warp = tid >> 5;
    const int wm = warp & 3, wn = warp >> 2;
    const int bh = blockIdx.y;
    const int q0 = blockIdx.x * 128;
    const int b = bh / HH, h = bh - b * HH;

    float acc[2][4][4];
#pragma unroll
    for (int i = 0; i < 2; i++)
#pragma unroll
        for (int j = 0; j < 4; j++)
#pragma unroll
            for (int u = 0; u < 4; u++) acc[i][j][u] = 0.f;

    const int o8 = lane >> 3;
    const unsigned a_off = ((wm * 32 + (lane & 15)) * PAD + (lane >> 4) * 8) * 2;
    // trans B: row = s, col = d
    const unsigned bt_row = (lane & 7) + (o8 & 1) * 8;
    const unsigned bt_col = wn * 32 + (o8 >> 1) * 8;

    for (int c = 0; c < 16; c++) {
        __syncthreads();
        {   // stage P chunk: 128 q-rows x 64 s fp32 -> split
            int row = tid >> 1, sh = (tid & 1) * 32;
            const float* g = prob + ((long)bh * SS + q0 + row) * SS + c * 64 + sh;
#pragma unroll
            for (int i = 0; i < 8; i++) {
                float4 v = *(const float4*)(g + i * 4);
                unsigned h0, l0, h1, l1;
                split_pair(v.x, v.y, h0, l0);
                split_pair(v.z, v.w, h1, l1);
                unsigned o = (row * PAD + sh + i * 4) * 2;
                *(unsigned*)(dynsm + PV_PH + o) = h0;
                *(unsigned*)(dynsm + PV_PH + o + 4) = h1;
                *(unsigned*)(dynsm + PV_PL + o) = l0;
                *(unsigned*)(dynsm + PV_PL + o + 4) = l1;
            }
        }
        {   // stage V chunk: 64 s-rows x 64 d bf16 (hi/lo)
            int s = tid >> 2, dq = (tid & 3) * 16;
            long idx = ((long)bh * SS + c * 64 + s) * HD + dq;
            unsigned so = (s * PAD + dq) * 2;
            *(float4*)(dynsm + PV_VH + so) = *(const float4*)(g_vh + idx);
            *(float4*)(dynsm + PV_VH + so + 16) = *(const float4*)(g_vh + idx + 8);
            *(float4*)(dynsm + PV_VL + so) = *(const float4*)(g_vl + idx);
            *(float4*)(dynsm + PV_VL + so + 16) = *(const float4*)(g_vl + idx + 8);
        }
        __syncthreads();

#pragma unroll
        for (int kk = 0; kk < 64; kk += 16) {
            unsigned Ah[2][4], Al[2][4], B[2][4];
            ldsm4(Ah[0], sbase + PV_PH + a_off + kk * 2);
            ldsm4(Ah[1], sbase + PV_PH + a_off + kk * 2 + 16 * ROWB);
            ldsm4(Al[0], sbase + PV_PL + a_off + kk * 2);
            ldsm4(Al[1], sbase + PV_PL + a_off + kk * 2 + 16 * ROWB);
            unsigned bo = ((kk + bt_row) * PAD + bt_col) * 2;
            ldsm4t(B[0], sbase + PV_VH + bo);
            ldsm4t(B[1], sbase + PV_VH + bo + 16 * 2);
#pragma unroll
            for (int mi = 0; mi < 2; mi++)
#pragma unroll
                for (int j = 0; j < 2; j++) {
                    mmabf(acc[mi][2 * j], Ah[mi], B[j][0], B[j][1]);
                    mmabf(acc[mi][2 * j + 1], Ah[mi], B[j][2], B[j][3]);
                }
#pragma unroll
            for (int mi = 0; mi < 2; mi++)
#pragma unroll
                for (int j = 0; j < 2; j++) {
                    mmabf(acc[mi][2 * j], Al[mi], B[j][0], B[j][1]);
                    mmabf(acc[mi][2 * j + 1], Al[mi], B[j][2], B[j][3]);
                }
            ldsm4t(B[0], sbase + PV_VL + bo);
            ldsm4t(B[1], sbase + PV_VL + bo + 16 * 2);
#pragma unroll
            for (int mi = 0; mi < 2; mi++)
#pragma unroll
                for (int j = 0; j < 2; j++) {
                    mmabf(acc[mi][2 * j], Ah[mi], B[j][0], B[j][1]);
                    mmabf(acc[mi][2 * j + 1], Ah[mi], B[j][2], B[j][3]);
                }
        }
    }

    const int r0 = lane >> 2, cp = (lane & 3) * 2;
#pragma unroll
    for (int mi = 0; mi < 2; mi++)
#pragma unroll
        for (int j2 = 0; j2 < 4; j2++) {
            int d = wn * 32 + j2 * 8 + cp;
#pragma unroll
            for (int half = 0; half < 2; half++) {
                int q = q0 + wm * 32 + mi * 16 + r0 + half * 8;
                float2 o;
                o.x = acc[mi][j2][half * 2];
                o.y = acc[mi][j2][half * 2 + 1];
                *(float2*)(out0 + ((long)(b * SS) + q) * DD + h * HD + d) = o;
            }
        }
}

// ---------------------------------------------------------------------------
extern "C" void kernel_launch(void* const* d_in, const int* in_sizes, int n_in,
                              void* d_out, int out_size)
{
    const float* query = (const float*)d_in[0];
    const float* key_t = (const float*)d_in[1];
    const float* value = (const float*)d_in[2];
    const float* rel   = (const float*)d_in[3];
    const void*  mask  = d_in[4];
    const float* l1    = (const float*)d_in[5];
    const float* Wq = (const float*)d_in[6];
    const float* bq = (const float*)d_in[7];
    const float* Wk = (const float*)d_in[8];
    const float* bk = (const float*)d_in[9];
    const float* Wv = (const float*)d_in[10];
    const float* bv = (const float*)d_in[11];

    float* out0 = (float*)d_out;                 // (B,S,D)
    float* prob = out0 + (long)BB * SS * DD;     // (B,H,S,S) scores->prob

    cudaFuncSetAttribute(proj_kernel,
                         cudaFuncAttributeMaxDynamicSharedMemorySize, PJ_SMEM);
    cudaFuncSetAttribute(score_kernel,
                         cudaFuncAttributeMaxDynamicSharedMemorySize, SC_SMEM);
    cudaFuncSetAttribute(pv_kernel,
                         cudaFuncAttributeMaxDynamicSharedMemorySize, PV_SMEM);

    detect_mask_kernel<<<1, 256>>>((const unsigned char*)mask);

    dim3 pgrid(HH, (BB * SS) / 128);
    proj_kernel<<<pgrid, 256, PJ_SMEM>>>(query, Wq, bq, 0);
    proj_kernel<<<pgrid, 256, PJ_SMEM>>>(key_t, Wk, bk, 1);
    proj_kernel<<<pgrid, 256, PJ_SMEM>>>(value, Wv, bv, 2);

    dim3 sgrid(SS / 128, SS / 128, NBH);
    score_kernel<<<sgrid, 256, SC_SMEM>>>(prob);

    dim3 smgrid(SS, BB);
    softmax_kernel<<<smgrid, 256>>>(rel, mask, l1, prob);

    dim3 vgrid(SS / 128, NBH);
    pv_kernel<<<vgrid, 256, PV_SMEM>>>(prob, out0);
}

// round 10
// speedup vs baseline: 3.3229x; 1.0767x over previous
#include <cuda_runtime.h>
#include <cuda_bf16.h>

// Problem constants
#define BB 8
#define SS 1024
#define DD 768
#define HH 12
#define HD 64
#define NBH (BB * HH)
#define MM (BB * SS)          // 8192 rows

// Scratch (no cudaMalloc allowed)
__device__ __nv_bfloat16 g_qh[NBH * SS * HD];   // (bh, s, d) projected splits
__device__ __nv_bfloat16 g_ql[NBH * SS * HD];
__device__ __nv_bfloat16 g_kh[NBH * SS * HD];
__device__ __nv_bfloat16 g_kl[NBH * SS * HD];
__device__ __nv_bfloat16 g_vh[NBH * SS * HD];
__device__ __nv_bfloat16 g_vl[NBH * SS * HD];
__device__ __nv_bfloat16 g_inh[3L * MM * DD];   // pre-split inputs (q,k,v)
__device__ __nv_bfloat16 g_inl[3L * MM * DD];
__device__ __nv_bfloat16 g_wh[3L * DD * DD];    // pre-split weights
__device__ __nv_bfloat16 g_wl[3L * DD * DD];
__device__ int g_mask_mode;                     // 0=f32, 1=i32, 2=u8

// ---------------------------------------------------------------------------
// Warp-MMA helpers (baseline PTX, no 'a'-gated features)
// ---------------------------------------------------------------------------
__device__ __forceinline__ unsigned smem_u32(const void* p) {
    unsigned a;
    asm("{ .reg .u64 t; cvta.to.shared.u64 t, %1; cvt.u32.u64 %0, t; }"
        : "=r"(a) : "l"(p));
    return a;
}
__device__ __forceinline__ void ldsm4(unsigned r[4], unsigned a) {
    asm volatile("ldmatrix.sync.aligned.m8n8.x4.shared.b16 {%0,%1,%2,%3}, [%4];"
                 : "=r"(r[0]), "=r"(r[1]), "=r"(r[2]), "=r"(r[3]) : "r"(a));
}
__device__ __forceinline__ void ldsm4t(unsigned r[4], unsigned a) {
    asm volatile("ldmatrix.sync.aligned.m8n8.x4.trans.shared.b16 {%0,%1,%2,%3}, [%4];"
                 : "=r"(r[0]), "=r"(r[1]), "=r"(r[2]), "=r"(r[3]) : "r"(a));
}
__device__ __forceinline__ void mmabf(float c[4], const unsigned a[4],
                                      unsigned b0, unsigned b1) {
    asm volatile("mma.sync.aligned.m16n8k16.row.col.f32.bf16.bf16.f32 "
                 "{%0,%1,%2,%3}, {%4,%5,%6,%7}, {%8,%9}, {%0,%1,%2,%3};"
                 : "+f"(c[0]), "+f"(c[1]), "+f"(c[2]), "+f"(c[3])
                 : "r"(a[0]), "r"(a[1]), "r"(a[2]), "r"(a[3]), "r"(b0), "r"(b1));
}

// split fp32 pair -> two packed-bf16 words (hi pair, lo pair)
__device__ __forceinline__ void split_pair(float a, float b, unsigned& hi, unsigned& lo) {
    __nv_bfloat162 h2 = __floats2bfloat162_rn(a, b);
    float ra = a - __bfloat162float(h2.x);
    float rb = b - __bfloat162float(h2.y);
    __nv_bfloat162 l2 = __floats2bfloat162_rn(ra, rb);
    hi = *(unsigned*)&h2;
    lo = *(unsigned*)&l2;
}

// padded smem row: 72 bf16 (144 B)
#define PAD 72
#define ROWB 144

// ---------------------------------------------------------------------------
// Pre-split: fp32 array -> bf16 hi/lo arrays. n multiple of 1024.
// ---------------------------------------------------------------------------
__global__ __launch_bounds__(256) void split_kernel(
    const float* __restrict__ src, __nv_bfloat16* __restrict__ dh,
    __nv_bfloat16* __restrict__ dl)
{
    long i = ((long)blockIdx.x * 256 + threadIdx.x) * 4;
    float4 v = *(const float4*)(src + i);
    unsigned h0, l0, h1, l1;
    split_pair(v.x, v.y, h0, l0);
    split_pair(v.z, v.w, h1, l1);
    *(uint2*)(dh + i) = make_uint2(h0, h1);
    *(uint2*)(dl + i) = make_uint2(l0, l1);
}

// ---------------------------------------------------------------------------
// Mask dtype detection
// ---------------------------------------------------------------------------
__global__ void detect_mask_kernel(const unsigned char* __restrict__ m) {
    __shared__ int f32flag, nz123;
    if (threadIdx.x == 0) { f32flag = 0; nz123 = 0; }
    __syncthreads();
    for (int i = threadIdx.x; i < 65536; i += blockDim.x) {
        unsigned char v = m[i];
        if (v) {
            int r = i & 3;
            if ((r == 3 && v == 0x3F) || (r == 2 && v == 0x80)) atomicOr(&f32flag, 1);
            if (r != 0) atomicOr(&nz123, 1);
        }
    }
    __syncthreads();
    if (threadIdx.x == 0)
        g_mask_mode = f32flag ? 0 : (nz123 ? 2 : 1);
}

__device__ __forceinline__ float maskAt(const void* m, long i, int mode) {
    if (mode == 0) return ((const float*)m)[i];
    if (mode == 1) return (float)((const int*)m)[i];
    return (float)((const unsigned char*)m)[i];
}

// ---------------------------------------------------------------------------
// Projection (HMMA): Y = X @ W^T + bias -> bf16 hi/lo splits [bh][s][d].
// Inputs pre-split bf16; staging = pure float4 copies.
// Block 256 thr = 8 warps (4m x 2n); tile 128m x 64n; K=768 in 12 chunks of 64.
// ---------------------------------------------------------------------------
#define PJ_BIAS 0
#define PJ_AH 256
#define PJ_AL (PJ_AH + 128 * ROWB)
#define PJ_BH (PJ_AL + 128 * ROWB)
#define PJ_BL (PJ_BH + 64 * ROWB)
#define PJ_SMEM (PJ_BL + 64 * ROWB)

__global__ __launch_bounds__(256, 2) void proj_kernel(
    const float* __restrict__ bias, int which)
{
    extern __shared__ char dynsm[];
    const unsigned sbase = smem_u32(dynsm);
    const int tid = threadIdx.x;
    const int lane = tid & 31, warp = tid >> 5;
    const int wm = warp & 3, wn = warp >> 2;     // 4m x 2n
    const int h = blockIdx.x;
    const int m0 = blockIdx.y * 128;
    const int n0 = h * HD;

    const __nv_bfloat16* Xh = g_inh + (long)which * MM * DD;
    const __nv_bfloat16* Xl = g_inl + (long)which * MM * DD;
    const __nv_bfloat16* Wh = g_wh + (long)which * DD * DD;
    const __nv_bfloat16* Wl = g_wl + (long)which * DD * DD;

    float* biasSm = (float*)(dynsm + PJ_BIAS);
    if (tid < 64) biasSm[tid] = bias[n0 + tid];

    float acc[2][4][4];
#pragma unroll
    for (int i = 0; i < 2; i++)
#pragma unroll
        for (int j = 0; j < 4; j++)
#pragma unroll
            for (int u = 0; u < 4; u++) acc[i][j][u] = 0.f;

    const int o8 = lane >> 3;
    const unsigned a_off = ((wm * 32 + (lane & 15)) * PAD + (lane >> 4) * 8) * 2;
    const unsigned b_off = ((wn * 32 + (lane & 7) + (o8 >> 1) * 8) * PAD + (o8 & 1) * 8) * 2;

    for (int c = 0; c < 12; c++) {
        __syncthreads();
        {   // stage X chunk: 128 rows x 64 k bf16 (hi/lo), pure copies
            int row = tid >> 1, kh = (tid & 1) * 32;
            long gi = (long)(m0 + row) * DD + c * 64 + kh;
            unsigned o = (row * PAD + kh) * 2;
#pragma unroll
            for (int i = 0; i < 4; i++) {
                *(float4*)(dynsm + PJ_AH + o + i * 16) = *(const float4*)(Xh + gi + i * 8);
                *(float4*)(dynsm + PJ_AL + o + i * 16) = *(const float4*)(Xl + gi + i * 8);
            }
        }
        {   // stage W chunk: 64 rows x 64 k bf16 (hi/lo)
            int n = tid >> 2, kq = (tid & 3) * 16;
            long gi = (long)(n0 + n) * DD + c * 64 + kq;
            unsigned o = (n * PAD + kq) * 2;
#pragma unroll
            for (int i = 0; i < 2; i++) {
                *(float4*)(dynsm + PJ_BH + o + i * 16) = *(const float4*)(Wh + gi + i * 8);
                *(float4*)(dynsm + PJ_BL + o + i * 16) = *(const float4*)(Wl + gi + i * 8);
            }
        }
        __syncthreads();

#pragma unroll
        for (int kk = 0; kk < 64; kk += 16) {
            unsigned Ah[2][4], Al[2][4], B[2][4];
            ldsm4(Ah[0], sbase + PJ_AH + a_off + kk * 2);
            ldsm4(Ah[1], sbase + PJ_AH + a_off + kk * 2 + 16 * ROWB);
            ldsm4(Al[0], sbase + PJ_AL + a_off + kk * 2);
            ldsm4(Al[1], sbase + PJ_AL + a_off + kk * 2 + 16 * ROWB);
            ldsm4(B[0], sbase + PJ_BH + b_off + kk * 2);
            ldsm4(B[1], sbase + PJ_BH + b_off + kk * 2 + 16 * ROWB);
#pragma unroll
            for (int mi = 0; mi < 2; mi++)
#pragma unroll
                for (int j = 0; j < 2; j++) {
                    mmabf(acc[mi][2 * j], Ah[mi], B[j][0], B[j][1]);
                    mmabf(acc[mi][2 * j + 1], Ah[mi], B[j][2], B[j][3]);
                }
#pragma unroll
            for (int mi = 0; mi < 2; mi++)
#pragma unroll
                for (int j = 0; j < 2; j++) {
                    mmabf(acc[mi][2 * j], Al[mi], B[j][0], B[j][1]);
                    mmabf(acc[mi][2 * j + 1], Al[mi], B[j][2], B[j][3]);
                }
            ldsm4(B[0], sbase + PJ_BL + b_off + kk * 2);
            ldsm4(B[1], sbase + PJ_BL + b_off + kk * 2 + 16 * ROWB);
#pragma unroll
            for (int mi = 0; mi < 2; mi++)
#pragma unroll
                for (int j = 0; j < 2; j++) {
                    mmabf(acc[mi][2 * j], Ah[mi], B[j][0], B[j][1]);
                    mmabf(acc[mi][2 * j + 1], Ah[mi], B[j][2], B[j][3]);
                }
        }
    }

    __nv_bfloat16* dh = (which == 0) ? g_qh : (which == 1) ? g_kh : g_vh;
    __nv_bfloat16* dl = (which == 0) ? g_ql : (which == 1) ? g_kl : g_vl;
    const int r0 = lane >> 2, cp = (lane & 3) * 2;
#pragma unroll
    for (int mi = 0; mi < 2; mi++)
#pragma unroll
        for (int j2 = 0; j2 < 4; j2++) {
            int d = wn * 32 + j2 * 8 + cp;
            float b0v = biasSm[d], b1v = biasSm[d + 1];
#pragma unroll
            for (int half = 0; half < 2; half++) {
                int m = m0 + wm * 32 + mi * 16 + r0 + half * 8;
                int b = m >> 10, s = m & 1023;
                long bh = (long)(b * HH + h);
                float y0 = acc[mi][j2][half * 2] + b0v;
                float y1 = acc[mi][j2][half * 2 + 1] + b1v;
                unsigned hv, lv;
                split_pair(y0, y1, hv, lv);
                long base = (bh * SS + s) * HD + d;
                *(unsigned*)(dh + base) = hv;
                *(unsigned*)(dl + base) = lv;
            }
        }
}

// ---------------------------------------------------------------------------
// Scores (HMMA): S = (Q K^T)/8 -> prob region (fp32 scratch).
// Block 256 thr = 8 warps (4m x 2n), tile 128q x 128k, warp 32q x 64k, K=64.
// ---------------------------------------------------------------------------
#define SC_QH 0
#define SC_QL (SC_QH + 128 * ROWB)
#define SC_KH (SC_QL + 128 * ROWB)
#define SC_KL (SC_KH + 128 * ROWB)
#define SC_SMEM (SC_KL + 128 * ROWB)

__global__ __launch_bounds__(256, 2) void score_kernel(float* __restrict__ prob)
{
    extern __shared__ char dynsm[];
    const unsigned sbase = smem_u32(dynsm);
    const int tid = threadIdx.x;
    const int lane = tid & 31, warp = tid >> 5;
    const int wm = warp & 3, wn = warp >> 2;
    const int bh = blockIdx.z;
    const int q0 = blockIdx.y * 128, k0 = blockIdx.x * 128;

    {   // stage 4 bf16 tiles: 128 rows x 64 d each
        int row = tid >> 1, hd0 = (tid & 1) * 32;
        long qrow = ((long)bh * SS + q0 + row) * HD + hd0;
        long krow = ((long)bh * SS + k0 + row) * HD + hd0;
        unsigned so = (row * PAD + hd0) * 2;
#pragma unroll
        for (int i = 0; i < 4; i++) {
            *(float4*)(dynsm + SC_QH + so + i * 16) = *(const float4*)(g_qh + qrow + i * 8);
            *(float4*)(dynsm + SC_QL + so + i * 16) = *(const float4*)(g_ql + qrow + i * 8);
            *(float4*)(dynsm + SC_KH + so + i * 16) = *(const float4*)(g_kh + krow + i * 8);
            *(float4*)(dynsm + SC_KL + so + i * 16) = *(const float4*)(g_kl + krow + i * 8);
        }
    }
    __syncthreads();

    float acc[2][8][4];
#pragma unroll
    for (int i = 0; i < 2; i++)
#pragma unroll
        for (int j = 0; j < 8; j++)
#pragma unroll
            for (int u = 0; u < 4; u++) acc[i][j][u] = 0.f;

    const int o8 = lane >> 3;
    const unsigned a_off = ((wm * 32 + (lane & 15)) * PAD + (lane >> 4) * 8) * 2;
    const unsigned b_off = ((wn * 64 + (lane & 7) + (o8 >> 1) * 8) * PAD + (o8 & 1) * 8) * 2;

#pragma unroll
    for (int kk = 0; kk < 64; kk += 16) {
        unsigned Ah[2][4], Al[2][4], B[4][4];
        ldsm4(Ah[0], sbase + SC_QH + a_off + kk * 2);
        ldsm4(Ah[1], sbase + SC_QH + a_off + kk * 2 + 16 * ROWB);
        ldsm4(Al[0], sbase + SC_QL + a_off + kk * 2);
        ldsm4(Al[1], sbase + SC_QL + a_off + kk * 2 + 16 * ROWB);
#pragma unroll
        for (int j = 0; j < 4; j++)
            ldsm4(B[j], sbase + SC_KH + b_off + kk * 2 + j * 16 * ROWB);
#pragma unroll
        for (int mi = 0; mi < 2; mi++)
#pragma unroll
            for (int j = 0; j < 4; j++) {
                mmabf(acc[mi][2 * j], Ah[mi], B[j][0], B[j][1]);
                mmabf(acc[mi][2 * j + 1], Ah[mi], B[j][2], B[j][3]);
            }
#pragma unroll
        for (int mi = 0; mi < 2; mi++)
#pragma unroll
            for (int j = 0; j < 4; j++) {
                mmabf(acc[mi][2 * j], Al[mi], B[j][0], B[j][1]);
                mmabf(acc[mi][2 * j + 1], Al[mi], B[j][2], B[j][3]);
            }
#pragma unroll
        for (int j = 0; j < 4; j++)
            ldsm4(B[j], sbase + SC_KL + b_off + kk * 2 + j * 16 * ROWB);
#pragma unroll
        for (int mi = 0; mi < 2; mi++)
#pragma unroll
            for (int j = 0; j < 4; j++) {
                mmabf(acc[mi][2 * j], Ah[mi], B[j][0], B[j][1]);
                mmabf(acc[mi][2 * j + 1], Ah[mi], B[j][2], B[j][3]);
            }
    }

    const int r0 = lane >> 2, cp = (lane & 3) * 2;
#pragma unroll
    for (int mi = 0; mi < 2; mi++)
#pragma unroll
        for (int j = 0; j < 8; j++) {
            int k = k0 + wn * 64 + j * 8 + cp;
#pragma unroll
            for (int half = 0; half < 2; half++) {
                int q = q0 + wm * 32 + mi * 16 + r0 + half * 8;
                float2 o;
                o.x = acc[mi][j][half * 2] * 0.125f;
                o.y = acc[mi][j][half * 2 + 1] * 0.125f;
                *(float2*)(prob + ((long)bh * SS + q) * SS + k) = o;
            }
        }
}

// ---------------------------------------------------------------------------
// Softmax + mask + rel-blend, in place on prob.
// Phase A: rel_attn once per (b,q) with block reductions.
// Phase B: warp-per-head (warp w -> heads w, w+8), shfl-only reductions.
// ---------------------------------------------------------------------------
__device__ __forceinline__ float bredMax(float v, volatile float* red) {
#pragma unroll
    for (int o = 16; o; o >>= 1) v = fmaxf(v, __shfl_xor_sync(0xffffffffu, v, o));
    if ((threadIdx.x & 31) == 0) red[threadIdx.x >> 5] = v;
    __syncthreads();
    float r = red[0];
#pragma unroll
    for (int i = 1; i < 8; i++) r = fmaxf(r, red[i]);
    __syncthreads();
    return r;
}
__device__ __forceinline__ float bredSum(float v, volatile float* red) {
#pragma unroll
    for (int o = 16; o; o >>= 1) v += __shfl_xor_sync(0xffffffffu, v, o);
    if ((threadIdx.x & 31) == 0) red[threadIdx.x >> 5] = v;
    __syncthreads();
    float r = 0.f;
#pragma unroll
    for (int i = 0; i < 8; i++) r += red[i];
    __syncthreads();
    return r;
}

__global__ __launch_bounds__(256) void softmax_kernel(
    const float* __restrict__ rel, const void* __restrict__ mask,
    const float* __restrict__ l1p, float* __restrict__ prob)
{
    __shared__ float relp[1024];   // l1 * rel_attn
    __shared__ float msk[1024];
    __shared__ float red[8];

    const int b = blockIdx.y, q = blockIdx.x, tid = threadIdx.x;
    const int mode = g_mask_mode;
    const long mbase = ((long)(b * SS + q)) * SS;

    // ---- Phase A: rel_attn row (head-independent), once ----
    float4 r4 = *(const float4*)(rel + mbase + tid * 4);
    float rr[4] = {r4.x, r4.y, r4.z, r4.w};
    float v[4], mv[4];
#pragma unroll
    for (int u = 0; u < 4; u++) {
        mv[u] = maskAt(mask, mbase + tid * 4 + u, mode);
        msk[tid * 4 + u] = mv[u];
        v[u] = (mv[u] != 0.f) ? rr[u] : -1.0e4f;
    }
    float mx = bredMax(fmaxf(fmaxf(v[0], v[1]), fmaxf(v[2], v[3])), red);
    float e[4], s = 0.f;
#pragma unroll
    for (int u = 0; u < 4; u++) { e[u] = __expf(v[u] - mx); s += e[u]; }
    float tot = bredSum(s, red);
    const float l1v = *l1p;
    const float w0 = 1.f - l1v;
    float li = l1v / tot;
#pragma unroll
    for (int u = 0; u < 4; u++) relp[tid * 4 + u] = e[u] * li;
    __syncthreads();

    // ---- Phase B: warp-per-head ----
    const int warp = tid >> 5, lane = tid & 31;
    for (int h = warp; h < HH; h += 8) {
        float* row = prob + (((long)(b * HH + h) * SS) + q) * SS;
        float sv[32];
        float hm = -3.0e38f;
#pragma unroll
        for (int i = 0; i < 8; i++) {
            int idx = i * 128 + lane * 4;
            float4 s4 = *(const float4*)(row + idx);
            float t0 = (msk[idx + 0] != 0.f) ? -1.0e9f : s4.x;
            float t1 = (msk[idx + 1] != 0.f) ? -1.0e9f : s4.y;
            float t2 = (msk[idx + 2] != 0.f) ? -1.0e9f : s4.z;
            float t3 = (msk[idx + 3] != 0.f) ? -1.0e9f : s4.w;
            sv[i * 4 + 0] = t0; sv[i * 4 + 1] = t1;
            sv[i * 4 + 2] = t2; sv[i * 4 + 3] = t3;
            hm = fmaxf(hm, fmaxf(fmaxf(t0, t1), fmaxf(t2, t3)));
        }
#pragma unroll
        for (int o = 16; o; o >>= 1) hm = fmaxf(hm, __shfl_xor_sync(0xffffffffu, hm, o));
        float hs = 0.f;
#pragma unroll
        for (int i = 0; i < 32; i++) {
            sv[i] = __expf(sv[i] - hm);
            hs += sv[i];
        }
#pragma unroll
        for (int o = 16; o; o >>= 1) hs += __shfl_xor_sync(0xffffffffu, hs, o);
        float wi = w0 / hs;
#pragma unroll
        for (int i = 0; i < 8; i++) {
            int idx = i * 128 + lane * 4;
            float4 o4;
            o4.x = sv[i * 4 + 0] * wi + relp[idx + 0];
            o4.y = sv[i * 4 + 1] * wi + relp[idx + 1];
            o4.z = sv[i * 4 + 2] * wi + relp[idx + 2];
            o4.w = sv[i * 4 + 3] * wi + relp[idx + 3];
            *(float4*)(row + idx) = o4;
        }
    }
}

// ---------------------------------------------------------------------------
// PV (HMMA): out[bh,q,d] = sum_s P[q][s] * V[s][d].
// Block 256 thr = 8 warps (4m x 2n), tile 128q x 64d, K=1024 in 16 chunks.
// ---------------------------------------------------------------------------
#define PV_PH 0
#define PV_PL (PV_PH + 128 * ROWB)
#define PV_VH (PV_PL + 128 * ROWB)
#define PV_VL (PV_VH + 64 * ROWB)
#define PV_SMEM (PV_VL + 64 * ROWB)

__global__ __launch_bounds__(256, 2) void pv_kernel(
    const float* __restrict__ prob, float* __restrict__ out0)
{
    extern __shared__ char dynsm[];
    const unsigned sbase = smem_u32(dynsm);
    const int tid = threadIdx.x;
    const int lane = tid & 31, warp = tid >> 5;
    const int wm = warp & 3, wn = warp >> 2;
    const int bh = blockIdx.y;
    const int q0 = blockIdx.x * 128;
    const int b = bh / HH, h = bh - b * HH;

    float acc[2][4][4];
#pragma unroll
    for (int i = 0; i < 2; i++)
#pragma unroll
        for (int j = 0; j < 4; j++)
#pragma unroll
            for (int u = 0; u < 4; u++) acc[i][j][u] = 0.f;

    const int o8 = lane >> 3;
    const unsigned a_off = ((wm * 32 + (lane & 15)) * PAD + (lane >> 4) * 8) * 2;
    const unsigned bt_row = (lane & 7) + (o8 & 1) * 8;
    const unsigned bt_col = wn * 32 + (o8 >> 1) * 8;

    for (int c = 0; c < 16; c++) {
        __syncthreads();
        {   // stage P chunk: 128 q-rows x 64 s fp32 -> split (uint2 stores)
            int row = tid >> 1, sh = (tid & 1) * 32;
            const float* g = prob + ((long)bh * SS + q0 + row) * SS + c * 64 + sh;
#pragma unroll
            for (int i = 0; i < 8; i++) {
                float4 v = *(const float4*)(g + i * 4);
                unsigned h0, l0, h1, l1;
                split_pair(v.x, v.y, h0, l0);
                split_pair(v.z, v.w, h1, l1);
                unsigned o = (row * PAD + sh + i * 4) * 2;
                *(uint2*)(dynsm + PV_PH + o) = make_uint2(h0, h1);
                *(uint2*)(dynsm + PV_PL + o) = make_uint2(l0, l1);
            }
        }
        {   // stage V chunk: 64 s-rows x 64 d bf16 (hi/lo)
            int s = tid >> 2, dq = (tid & 3) * 16;
            long idx = ((long)bh * SS + c * 64 + s) * HD + dq;
            unsigned so = (s * PAD + dq) * 2;
            *(float4*)(dynsm + PV_VH + so) = *(const float4*)(g_vh + idx);
            *(float4*)(dynsm + PV_VH + so + 16) = *(const float4*)(g_vh + idx + 8);
            *(float4*)(dynsm + PV_VL + so) = *(const float4*)(g_vl + idx);
            *(float4*)(dynsm + PV_VL + so + 16) = *(const float4*)(g_vl + idx + 8);
        }
        __syncthreads();

#pragma unroll
        for (int kk = 0; kk < 64; kk += 16) {
            unsigned Ah[2][4], Al[2][4], B[2][4];
            ldsm4(Ah[0], sbase + PV_PH + a_off + kk * 2);
            ldsm4(Ah[1], sbase + PV_PH + a_off + kk * 2 + 16 * ROWB);
            ldsm4(Al[0], sbase + PV_PL + a_off + kk * 2);
            ldsm4(Al[1], sbase + PV_PL + a_off + kk * 2 + 16 * ROWB);
            unsigned bo = ((kk + bt_row) * PAD + bt_col) * 2;
            ldsm4t(B[0], sbase + PV_VH + bo);
            ldsm4t(B[1], sbase + PV_VH + bo + 16 * 2);
#pragma unroll
            for (int mi = 0; mi < 2; mi++)
#pragma unroll
                for (int j = 0; j < 2; j++) {
                    mmabf(acc[mi][2 * j], Ah[mi], B[j][0], B[j][1]);
                    mmabf(acc[mi][2 * j + 1], Ah[mi], B[j][2], B[j][3]);
                }
#pragma unroll
            for (int mi = 0; mi < 2; mi++)
#pragma unroll
                for (int j = 0; j < 2; j++) {
                    mmabf(acc[mi][2 * j], Al[mi], B[j][0], B[j][1]);
                    mmabf(acc[mi][2 * j + 1], Al[mi], B[j][2], B[j][3]);
                }
            ldsm4t(B[0], sbase + PV_VL + bo);
            ldsm4t(B[1], sbase + PV_VL + bo + 16 * 2);
#pragma unroll
            for (int mi = 0; mi < 2; mi++)
#pragma unroll
                for (int j = 0; j < 2; j++) {
                    mmabf(acc[mi][2 * j], Ah[mi], B[j][0], B[j][1]);
                    mmabf(acc[mi][2 * j + 1], Ah[mi], B[j][2], B[j][3]);
                }
        }
    }

    const int r0 = lane >> 2, cp = (lane & 3) * 2;
#pragma unroll
    for (int mi = 0; mi < 2; mi++)
#pragma unroll
        for (int j2 = 0; j2 < 4; j2++) {
            int d = wn * 32 + j2 * 8 + cp;
#pragma unroll
            for (int half = 0; half < 2; half++) {
                int q = q0 + wm * 32 + mi * 16 + r0 + half * 8;
                float2 o;
                o.x = acc[mi][j2][half * 2];
                o.y = acc[mi][j2][half * 2 + 1];
                *(float2*)(out0 + ((long)(b * SS) + q) * DD + h * HD + d) = o;
            }
        }
}

// ---------------------------------------------------------------------------
extern "C" void kernel_launch(void* const* d_in, const int* in_sizes, int n_in,
                              void* d_out, int out_size)
{
    const float* query = (const float*)d_in[0];
    const float* key_t = (const float*)d_in[1];
    const float* value = (const float*)d_in[2];
    const float* rel   = (const float*)d_in[3];
    const void*  mask  = d_in[4];
    const float* l1    = (const float*)d_in[5];
    const float* Wq = (const float*)d_in[6];
    const float* bq = (const float*)d_in[7];
    const float* Wk = (const float*)d_in[8];
    const float* bk = (const float*)d_in[9];
    const float* Wv = (const float*)d_in[10];
    const float* bv = (const float*)d_in[11];

    float* out0 = (float*)d_out;                 // (B,S,D)
    float* prob = out0 + (long)BB * SS * DD;     // (B,H,S,S) scores->prob

    cudaFuncSetAttribute(proj_kernel,
                         cudaFuncAttributeMaxDynamicSharedMemorySize, PJ_SMEM);
    cudaFuncSetAttribute(score_kernel,
                         cudaFuncAttributeMaxDynamicSharedMemorySize, SC_SMEM);
    cudaFuncSetAttribute(pv_kernel,
                         cudaFuncAttributeMaxDynamicSharedMemorySize, PV_SMEM);

    detect_mask_kernel<<<1, 256>>>((const unsigned char*)mask);

    // Pre-split inputs and weights into bf16 hi/lo
    __nv_bfloat16 *inh, *inl, *wh, *wl;
    cudaGetSymbolAddress((void**)&inh, g_inh);
    cudaGetSymbolAddress((void**)&inl, g_inl);
    cudaGetSymbolAddress((void**)&wh, g_wh);
    cudaGetSymbolAddress((void**)&wl, g_wl);
    const long XN = (long)MM * DD, WN = (long)DD * DD;
    split_kernel<<<XN / 1024, 256>>>(query, inh, inl);
    split_kernel<<<XN / 1024, 256>>>(key_t, inh + XN, inl + XN);
    split_kernel<<<XN / 1024, 256>>>(value, inh + 2 * XN, inl + 2 * XN);
    split_kernel<<<WN / 1024, 256>>>(Wq, wh, wl);
    split_kernel<<<WN / 1024, 256>>>(Wk, wh + WN, wl + WN);
    split_kernel<<<WN / 1024, 256>>>(Wv, wh + 2 * WN, wl + 2 * WN);

    dim3 pgrid(HH, MM / 128);
    proj_kernel<<<pgrid, 256, PJ_SMEM>>>(bq, 0);
    proj_kernel<<<pgrid, 256, PJ_SMEM>>>(bk, 1);
    proj_kernel<<<pgrid, 256, PJ_SMEM>>>(bv, 2);

    dim3 sgrid(SS / 128, SS / 128, NBH);
    score_kernel<<<sgrid, 256, SC_SMEM>>>(prob);

    dim3 smgrid(SS, BB);
    softmax_kernel<<<smgrid, 256>>>(rel, mask, l1, prob);

    dim3 vgrid(SS / 128, NBH);
    pv_kernel<<<vgrid, 256, PV_SMEM>>>(prob, out0);
}